// round 1
// baseline (speedup 1.0000x reference)
#include <cuda_runtime.h>
#include <math.h>

#define N_NODES  100000
#define N_EDGES  1600000
#define N_GRAPHS 2048
#define SCAN_BLOCKS ((N_NODES + 1023) / 1024)   // 98

// ---------------- scratch (device globals: no allocation allowed) ----------
__device__ float g_buf1[(size_t)N_NODES * 384];
__device__ float g_buf2[(size_t)N_NODES * 384];
__device__ int   g_deg[N_NODES];
__device__ int   g_rowstart[N_NODES + 1];
__device__ int   g_cursor[N_NODES];
__device__ int   g_csr[N_EDGES];
__device__ float g_dinv[N_NODES];
__device__ int   g_gcnt[N_GRAPHS];
__device__ int   g_gstart[N_GRAPHS + 1];
__device__ int   g_bsums[128];

// ---------------- init / histograms ---------------------------------------
__global__ void k_init() {
    int i = blockIdx.x * blockDim.x + threadIdx.x;
    if (i < N_NODES)  g_deg[i] = 0;
    if (i < N_GRAPHS) g_gcnt[i] = 0;
}

__global__ void k_hist_deg(const int* __restrict__ dst) {
    int e = blockIdx.x * blockDim.x + threadIdx.x;
    if (e < N_EDGES) atomicAdd(&g_deg[dst[e]], 1);
}

__global__ void k_hist_batch(const int* __restrict__ batch) {
    int i = blockIdx.x * blockDim.x + threadIdx.x;
    if (i < N_NODES) atomicAdd(&g_gcnt[batch[i]], 1);
}

// ---------------- generic exclusive scan (3 kernels) -----------------------
__global__ void k_scan_block(const int* __restrict__ in, int* __restrict__ out,
                             int n, int* __restrict__ bsums) {
    __shared__ int sm[1024];
    int i = blockIdx.x * 1024 + threadIdx.x;
    int v = (i < n) ? in[i] : 0;
    sm[threadIdx.x] = v;
    __syncthreads();
    for (int off = 1; off < 1024; off <<= 1) {
        int t = (threadIdx.x >= off) ? sm[threadIdx.x - off] : 0;
        __syncthreads();
        sm[threadIdx.x] += t;
        __syncthreads();
    }
    if (i < n) out[i] = sm[threadIdx.x] - v;           // exclusive
    if (threadIdx.x == 1023) bsums[blockIdx.x] = sm[1023];
}

__global__ void k_scan_sums(int* __restrict__ bsums, int nb) {  // 1 block, 128 thr
    __shared__ int sm[128];
    int v = (threadIdx.x < nb) ? bsums[threadIdx.x] : 0;
    sm[threadIdx.x] = v;
    __syncthreads();
    for (int off = 1; off < 128; off <<= 1) {
        int t = (threadIdx.x >= off) ? sm[threadIdx.x - off] : 0;
        __syncthreads();
        sm[threadIdx.x] += t;
        __syncthreads();
    }
    if (threadIdx.x < nb) bsums[threadIdx.x] = sm[threadIdx.x] - v;  // exclusive
}

__global__ void k_scan_add(int* __restrict__ out, int n,
                           const int* __restrict__ bsums, int total,
                           int* __restrict__ cursor) {
    int i = blockIdx.x * 1024 + threadIdx.x;
    if (i < n) {
        int v = out[i] + bsums[blockIdx.x];
        out[i] = v;
        if (cursor) cursor[i] = v;
    }
    if (i == 0) out[n] = total;
}

// ---------------- dinv + CSR fill ------------------------------------------
__global__ void k_dinv() {
    int i = blockIdx.x * blockDim.x + threadIdx.x;
    if (i < N_NODES) g_dinv[i] = rsqrtf((float)g_deg[i] + 1.0f);
}

__global__ void k_fill(const int* __restrict__ src, const int* __restrict__ dst) {
    int e = blockIdx.x * blockDim.x + threadIdx.x;
    if (e < N_EDGES) {
        int d = dst[e];
        int p = atomicAdd(&g_cursor[d], 1);
        g_csr[p] = src[e];
    }
}

// ---------------- SGEMM: C[M,N] = A[M,K] @ B[K,N] --------------------------
#define BM 64
#define BN 64
#define BK 8
__global__ void k_gemm(const float* __restrict__ A, const float* __restrict__ B,
                       float* __restrict__ C, int M, int N, int K) {
    __shared__ float As[BK][BM + 4];
    __shared__ float Bs[BK][BN];
    int tid = threadIdx.x;            // 0..255
    int tx = tid % 16, ty = tid / 16;
    int rowBase = blockIdx.y * BM;
    int colBase = blockIdx.x * BN;
    float acc[4][4] = {};
    for (int k0 = 0; k0 < K; k0 += BK) {
#pragma unroll
        for (int t = 0; t < 2; t++) {
            int idx = tid + t * 256;
            int r = idx / BK, c = idx % BK;
            int gr = rowBase + r, gc = k0 + c;
            As[c][r] = (gr < M && gc < K) ? A[(size_t)gr * K + gc] : 0.0f;
        }
#pragma unroll
        for (int t = 0; t < 2; t++) {
            int idx = tid + t * 256;
            int r = idx / BN, c = idx % BN;
            int gr = k0 + r, gc = colBase + c;
            Bs[r][c] = (gr < K && gc < N) ? B[(size_t)gr * N + gc] : 0.0f;
        }
        __syncthreads();
#pragma unroll
        for (int k = 0; k < BK; k++) {
            float a[4], b[4];
#pragma unroll
            for (int i = 0; i < 4; i++) a[i] = As[k][ty * 4 + i];
#pragma unroll
            for (int j = 0; j < 4; j++) b[j] = Bs[k][tx * 4 + j];
#pragma unroll
            for (int i = 0; i < 4; i++)
#pragma unroll
                for (int j = 0; j < 4; j++)
                    acc[i][j] += a[i] * b[j];
        }
        __syncthreads();
    }
#pragma unroll
    for (int i = 0; i < 4; i++) {
        int r = rowBase + ty * 4 + i;
        if (r < M) {
#pragma unroll
            for (int j = 0; j < 4; j++) {
                int c = colBase + tx * 4 + j;
                if (c < N) C[(size_t)r * N + c] = acc[i][j];
            }
        }
    }
}

// ---------------- aggregate (+bias, +BN, +ReLU), one block per node --------
template <int F, bool BNRELU>
__global__ void k_aggregate(const float* __restrict__ xw, float* __restrict__ h,
                            const float* __restrict__ bias,
                            const float* __restrict__ gamma,
                            const float* __restrict__ beta,
                            const float* __restrict__ rm,
                            const float* __restrict__ rv) {
    constexpr int CPT = F / 128;
    int i = blockIdx.x;
    int tx = threadIdx.x;
    int rs = g_rowstart[i], re = g_rowstart[i + 1];
    float di = g_dinv[i];
    float acc[CPT];
    float self = di * di;
#pragma unroll
    for (int c = 0; c < CPT; c++)
        acc[c] = xw[(size_t)i * F + tx + c * 128] * self;
    for (int e = rs; e < re; e++) {
        int s = g_csr[e];
        float nrm = g_dinv[s] * di;
#pragma unroll
        for (int c = 0; c < CPT; c++)
            acc[c] += xw[(size_t)s * F + tx + c * 128] * nrm;
    }
#pragma unroll
    for (int c = 0; c < CPT; c++) {
        int col = tx + c * 128;
        float v = acc[c] + bias[col];
        if (BNRELU) {
            v = (v - rm[col]) * rsqrtf(rv[col] + 1e-5f) * gamma[col] + beta[col];
            v = fmaxf(v, 0.0f);
        }
        h[(size_t)i * F + col] = v;
    }
}

// ---------------- pooling: mean + max per graph ----------------------------
__global__ void k_pool(const float* __restrict__ h3, float* __restrict__ out) {
    int g = blockIdx.x;
    int tx = threadIdx.x;
    int s = g_gstart[g], e = g_gstart[g + 1];
    float sum[3] = {0.f, 0.f, 0.f};
    float mx[3]  = {-INFINITY, -INFINITY, -INFINITY};
    for (int n = s; n < e; n++) {
#pragma unroll
        for (int c = 0; c < 3; c++) {
            float v = h3[(size_t)n * 384 + tx + c * 128];
            sum[c] += v;
            mx[c] = fmaxf(mx[c], v);
        }
    }
    float inv = 1.0f / fmaxf((float)(e - s), 1.0f);
#pragma unroll
    for (int c = 0; c < 3; c++)
        out[(size_t)g * 384 + tx + c * 128] = sum[c] * inv + mx[c];
}

// ---------------- launch ----------------------------------------------------
extern "C" void kernel_launch(void* const* d_in, const int* in_sizes, int n_in,
                              void* d_out, int out_size) {
    const float* x     = (const float*)d_in[0];
    const int*   ei    = (const int*)d_in[1];   // [2, E] int32
    const int*   src   = ei;
    const int*   dst   = ei + N_EDGES;
    const int*   batch = (const int*)d_in[2];
    const float* W1 = (const float*)d_in[3];
    const float* b1 = (const float*)d_in[4];
    const float* g1 = (const float*)d_in[5];
    const float* be1 = (const float*)d_in[6];
    const float* rm1 = (const float*)d_in[7];
    const float* rv1 = (const float*)d_in[8];
    const float* W2 = (const float*)d_in[9];
    const float* b2 = (const float*)d_in[10];
    const float* g2 = (const float*)d_in[11];
    const float* be2 = (const float*)d_in[12];
    const float* rm2 = (const float*)d_in[13];
    const float* rv2 = (const float*)d_in[14];
    const float* W3 = (const float*)d_in[15];
    const float* b3 = (const float*)d_in[16];
    float* out = (float*)d_out;

    float *p_buf1, *p_buf2;
    int *p_deg, *p_rowstart, *p_cursor, *p_gcnt, *p_gstart, *p_bsums;
    cudaGetSymbolAddress((void**)&p_buf1, g_buf1);
    cudaGetSymbolAddress((void**)&p_buf2, g_buf2);
    cudaGetSymbolAddress((void**)&p_deg, g_deg);
    cudaGetSymbolAddress((void**)&p_rowstart, g_rowstart);
    cudaGetSymbolAddress((void**)&p_cursor, g_cursor);
    cudaGetSymbolAddress((void**)&p_gcnt, g_gcnt);
    cudaGetSymbolAddress((void**)&p_gstart, g_gstart);
    cudaGetSymbolAddress((void**)&p_bsums, g_bsums);

    // ---- CSR + pooling segment construction (rebuilt every call) ----
    k_init<<<(N_NODES + 255) / 256, 256>>>();
    k_hist_deg<<<(N_EDGES + 255) / 256, 256>>>(dst);
    k_hist_batch<<<(N_NODES + 255) / 256, 256>>>(batch);

    k_scan_block<<<SCAN_BLOCKS, 1024>>>(p_deg, p_rowstart, N_NODES, p_bsums);
    k_scan_sums<<<1, 128>>>(p_bsums, SCAN_BLOCKS);
    k_scan_add<<<SCAN_BLOCKS, 1024>>>(p_rowstart, N_NODES, p_bsums, N_EDGES, p_cursor);

    k_dinv<<<(N_NODES + 255) / 256, 256>>>();
    k_fill<<<(N_EDGES + 255) / 256, 256>>>(src, dst);

    k_scan_block<<<2, 1024>>>(p_gcnt, p_gstart, N_GRAPHS, p_bsums);
    k_scan_sums<<<1, 128>>>(p_bsums, 2);
    k_scan_add<<<2, 1024>>>(p_gstart, N_GRAPHS, p_bsums, N_NODES, (int*)0);

    // ---- Layer 1: [100000,74]@[74,256] -> agg+BN+ReLU ----
    {
        dim3 grid((256 + BN - 1) / BN, (N_NODES + BM - 1) / BM);
        k_gemm<<<grid, 256>>>(x, W1, p_buf1, N_NODES, 256, 74);
        k_aggregate<256, true><<<N_NODES, 128>>>(p_buf1, p_buf2, b1, g1, be1, rm1, rv1);
    }
    // ---- Layer 2: [100000,256]@[256,256] -> agg+BN+ReLU ----
    {
        dim3 grid((256 + BN - 1) / BN, (N_NODES + BM - 1) / BM);
        k_gemm<<<grid, 256>>>(p_buf2, W2, p_buf1, N_NODES, 256, 256);
        k_aggregate<256, true><<<N_NODES, 128>>>(p_buf1, p_buf2, b2, g2, be2, rm2, rv2);
    }
    // ---- Layer 3: [100000,256]@[256,384] -> agg (no BN/ReLU) ----
    {
        dim3 grid((384 + BN - 1) / BN, (N_NODES + BM - 1) / BM);
        k_gemm<<<grid, 256>>>(p_buf2, W3, p_buf1, N_NODES, 384, 256);
        k_aggregate<384, false><<<N_NODES, 128>>>(p_buf1, p_buf2, b3, (const float*)0,
                                                  (const float*)0, (const float*)0,
                                                  (const float*)0);
    }
    // ---- mean+max pool ----
    k_pool<<<N_GRAPHS, 128>>>(p_buf2, out);
}

// round 3
// speedup vs baseline: 1.3547x; 1.3547x over previous
#include <cuda_runtime.h>
#include <cuda_bf16.h>
#include <math.h>
#include <cstdint>

#define N_NODES  100000
#define N_EDGES  1600000
#define N_GRAPHS 2048
#define SCAN_BLOCKS ((N_NODES + 1023) / 1024)   // 98
#define MPAD 100096                              // 782 * 128

// ---------------- scratch (device globals: no allocation allowed) ----------
__device__ float g_buf1[(size_t)N_NODES * 384];            // GEMM output xw
__device__ float g_buf2[(size_t)N_NODES * 384];            // aggregate output h
__device__ __nv_bfloat16 g_Aaug[(size_t)MPAD * 768];       // [MPAD, 3*KS]
__device__ __nv_bfloat16 g_Baug[(size_t)384 * 768];        // [NTOT, 3*KS]
__device__ int   g_deg[N_NODES];
__device__ int   g_rowstart[N_NODES + 1];
__device__ int   g_cursor[N_NODES];
__device__ int   g_csr[N_EDGES];
__device__ float g_dinv[N_NODES];
__device__ int   g_gcnt[N_GRAPHS];
__device__ int   g_gstart[N_GRAPHS + 1];
__device__ int   g_bsums[128];

// ======================= low-level helpers ==================================
__device__ __forceinline__ uint32_t smem_u32(const void* p) {
    uint32_t a;
    asm("{ .reg .u64 t; cvta.to.shared.u64 t, %1; cvt.u32.u64 %0, t; }"
        : "=r"(a) : "l"(p));
    return a;
}

__device__ __forceinline__ void cp_async16(uint32_t dst, const void* src) {
    asm volatile("cp.async.cg.shared.global [%0], [%1], 16;"
                 :: "r"(dst), "l"(src));
}
__device__ __forceinline__ void cp_commit() {
    asm volatile("cp.async.commit_group;");
}
__device__ __forceinline__ void cp_wait1() {
    asm volatile("cp.async.wait_group 1;");
}
__device__ __forceinline__ void cp_wait0() {
    asm volatile("cp.async.wait_group 0;");
}

__device__ __forceinline__ void ldsm_x4(uint32_t& r0, uint32_t& r1,
                                        uint32_t& r2, uint32_t& r3, uint32_t addr) {
    asm volatile("ldmatrix.sync.aligned.m8n8.x4.shared.b16 {%0,%1,%2,%3}, [%4];"
                 : "=r"(r0), "=r"(r1), "=r"(r2), "=r"(r3) : "r"(addr));
}

__device__ __forceinline__ void mma16816(float* c, const uint32_t* a, const uint32_t* b) {
    asm volatile(
        "mma.sync.aligned.m16n8k16.row.col.f32.bf16.bf16.f32 "
        "{%0,%1,%2,%3}, {%4,%5,%6,%7}, {%8,%9}, {%0,%1,%2,%3};"
        : "+f"(c[0]), "+f"(c[1]), "+f"(c[2]), "+f"(c[3])
        : "r"(a[0]), "r"(a[1]), "r"(a[2]), "r"(a[3]), "r"(b[0]), "r"(b[1]));
}

// ---------------- init / histograms ---------------------------------------
__global__ void k_init() {
    int i = blockIdx.x * blockDim.x + threadIdx.x;
    if (i < N_NODES)  g_deg[i] = 0;
    if (i < N_GRAPHS) g_gcnt[i] = 0;
}

__global__ void k_hist_deg(const int* __restrict__ dst) {
    int e = blockIdx.x * blockDim.x + threadIdx.x;
    if (e < N_EDGES) atomicAdd(&g_deg[dst[e]], 1);
}

__global__ void k_hist_batch(const int* __restrict__ batch) {
    int i = blockIdx.x * blockDim.x + threadIdx.x;
    if (i < N_NODES) atomicAdd(&g_gcnt[batch[i]], 1);
}

// ---------------- generic exclusive scan (3 kernels) -----------------------
__global__ void k_scan_block(const int* __restrict__ in, int* __restrict__ out,
                             int n, int* __restrict__ bsums) {
    __shared__ int sm[1024];
    int i = blockIdx.x * 1024 + threadIdx.x;
    int v = (i < n) ? in[i] : 0;
    sm[threadIdx.x] = v;
    __syncthreads();
    for (int off = 1; off < 1024; off <<= 1) {
        int t = (threadIdx.x >= off) ? sm[threadIdx.x - off] : 0;
        __syncthreads();
        sm[threadIdx.x] += t;
        __syncthreads();
    }
    if (i < n) out[i] = sm[threadIdx.x] - v;           // exclusive
    if (threadIdx.x == 1023) bsums[blockIdx.x] = sm[1023];
}

__global__ void k_scan_sums(int* __restrict__ bsums, int nb) {  // 1 block, 128 thr
    __shared__ int sm[128];
    int v = (threadIdx.x < nb) ? bsums[threadIdx.x] : 0;
    sm[threadIdx.x] = v;
    __syncthreads();
    for (int off = 1; off < 128; off <<= 1) {
        int t = (threadIdx.x >= off) ? sm[threadIdx.x - off] : 0;
        __syncthreads();
        sm[threadIdx.x] += t;
        __syncthreads();
    }
    if (threadIdx.x < nb) bsums[threadIdx.x] = sm[threadIdx.x] - v;  // exclusive
}

__global__ void k_scan_add(int* __restrict__ out, int n,
                           const int* __restrict__ bsums, int total,
                           int* __restrict__ cursor) {
    int i = blockIdx.x * 1024 + threadIdx.x;
    if (i < n) {
        int v = out[i] + bsums[blockIdx.x];
        out[i] = v;
        if (cursor) cursor[i] = v;
    }
    if (i == 0) out[n] = total;
}

// ---------------- dinv + CSR fill ------------------------------------------
__global__ void k_dinv() {
    int i = blockIdx.x * blockDim.x + threadIdx.x;
    if (i < N_NODES) g_dinv[i] = rsqrtf((float)g_deg[i] + 1.0f);
}

__global__ void k_fill(const int* __restrict__ src, const int* __restrict__ dst) {
    int e = blockIdx.x * blockDim.x + threadIdx.x;
    if (e < N_EDGES) {
        int d = dst[e];
        int p = atomicAdd(&g_cursor[d], 1);
        g_csr[p] = src[e];
    }
}

// ---------------- fp32 -> augmented bf16 conversions -----------------------
// Aaug[r, 0:KS)=hi, [KS,2KS)=lo, [2KS,3KS)=hi   (zero padded rows/cols)
__global__ void k_convA(const float* __restrict__ X,
                        __nv_bfloat16* __restrict__ Aaug,
                        int M, int Kreal, int KS) {
    size_t idx = (size_t)blockIdx.x * blockDim.x + threadIdx.x;
    size_t total = (size_t)MPAD * KS;
    if (idx >= total) return;
    int r = (int)(idx / KS);
    int k = (int)(idx % KS);
    float v = (r < M && k < Kreal) ? X[(size_t)r * Kreal + k] : 0.0f;
    __nv_bfloat16 h = __float2bfloat16(v);
    __nv_bfloat16 l = __float2bfloat16(v - __bfloat162float(h));
    size_t base = (size_t)r * (3 * KS) + k;
    Aaug[base]          = h;
    Aaug[base + KS]     = l;
    Aaug[base + 2 * KS] = h;
}

// Baug[n, 0:KS)=hi, [KS,2KS)=hi, [2KS,3KS)=lo ;  B from W[K,N] (transposed)
__global__ void k_convB(const float* __restrict__ W,
                        __nv_bfloat16* __restrict__ Baug,
                        int Kreal, int N, int KS) {
    size_t idx = (size_t)blockIdx.x * blockDim.x + threadIdx.x;
    size_t total = (size_t)N * KS;
    if (idx >= total) return;
    int n = (int)(idx / KS);
    int k = (int)(idx % KS);
    float v = (k < Kreal) ? W[(size_t)k * N + n] : 0.0f;
    __nv_bfloat16 h = __float2bfloat16(v);
    __nv_bfloat16 l = __float2bfloat16(v - __bfloat162float(h));
    size_t base = (size_t)n * (3 * KS) + k;
    Baug[base]          = h;
    Baug[base + KS]     = h;
    Baug[base + 2 * KS] = l;
}

// ---------------- bf16 mma.sync GEMM ----------------------------------------
// C[MPAD, NTOT] = Aaug[MPAD, K] @ Baug[NTOT, K]^T  (both K-major)
// Block 128x128x32, 8 warps (2x4), warp tile 64x32, m16n8k16 fragments.
#define GS 40   // smem row stride in bf16 (32 data + 8 pad = 80B, conflict-free)

__global__ __launch_bounds__(256, 1)
void k_gemm_mma(const __nv_bfloat16* __restrict__ A,
                const __nv_bfloat16* __restrict__ B,
                float* __restrict__ C, int K, int NTOT) {
    __shared__ __align__(16) __nv_bfloat16 As[2][128 * GS];
    __shared__ __align__(16) __nv_bfloat16 Bs[2][128 * GS];

    int tid = threadIdx.x;
    int wid = tid >> 5, lane = tid & 31;
    int warp_m = wid & 1;          // 2 warps along M (64 rows each)
    int warp_n = wid >> 1;         // 4 warps along N (32 cols each)
    int rowBase = blockIdx.y * 128;
    int colBase = blockIdx.x * 128;

    uint32_t asb = smem_u32(&As[0][0]);
    uint32_t bsb = smem_u32(&Bs[0][0]);
    const uint32_t bufBytes = 128 * GS * 2;

    float acc[4][4][4];
#pragma unroll
    for (int i = 0; i < 4; i++)
#pragma unroll
        for (int j = 0; j < 4; j++)
#pragma unroll
            for (int q = 0; q < 4; q++) acc[i][j][q] = 0.0f;

    const int NC = K >> 5;   // 32-wide K chunks

    // ---- async load of one chunk into buffer `buf` ----
    auto load_chunk = [&](int c, int buf) {
        int k0 = c << 5;
#pragma unroll
        for (int t = 0; t < 2; t++) {
            int idx = tid + (t << 8);             // 0..511
            int r = idx >> 2, seg = idx & 3;      // row 0..127, 16B segment 0..3
            uint32_t doff = (uint32_t)(r * GS + seg * 8) * 2;
            cp_async16(asb + buf * bufBytes + doff,
                       A + (size_t)(rowBase + r) * K + k0 + seg * 8);
            cp_async16(bsb + buf * bufBytes + doff,
                       B + (size_t)(colBase + r) * K + k0 + seg * 8);
        }
        cp_commit();
    };

    load_chunk(0, 0);

    for (int c = 0; c < NC; c++) {
        int buf = c & 1;
        if (c + 1 < NC) {
            load_chunk(c + 1, buf ^ 1);
            cp_wait1();
        } else {
            cp_wait0();
        }
        __syncthreads();

        uint32_t aBase = asb + buf * bufBytes;
        uint32_t bBase = bsb + buf * bufBytes;
#pragma unroll
        for (int kk = 0; kk < 2; kk++) {
            // A fragments: 4 m16 tiles
            uint32_t af[4][4];
            {
                int row = warp_m * 64 + (lane & 15);
                int kcol = kk * 16 + ((lane >> 4) << 3);
#pragma unroll
                for (int i = 0; i < 4; i++) {
                    uint32_t addr = aBase + (uint32_t)((row + i * 16) * GS + kcol) * 2;
                    ldsm_x4(af[i][0], af[i][1], af[i][2], af[i][3], addr);
                }
            }
            // B fragments: 4 n8 tiles via 2 x ldmatrix.x4
            uint32_t bf[4][2];
            {
                int rown = warp_n * 32 + (lane & 7) + ((lane & 16) ? 8 : 0);
                int kcol = kk * 16 + ((lane & 8) ? 8 : 0);
#pragma unroll
                for (int jj = 0; jj < 2; jj++) {
                    uint32_t addr = bBase + (uint32_t)((rown + jj * 16) * GS + kcol) * 2;
                    ldsm_x4(bf[jj * 2][0], bf[jj * 2][1],
                            bf[jj * 2 + 1][0], bf[jj * 2 + 1][1], addr);
                }
            }
#pragma unroll
            for (int i = 0; i < 4; i++)
#pragma unroll
                for (int j = 0; j < 4; j++)
                    mma16816(acc[i][j], af[i], bf[j]);
        }
        __syncthreads();
    }

    // ---- epilogue ----
    int mrow0 = rowBase + warp_m * 64 + (lane >> 2);
    int ncol0 = colBase + warp_n * 32 + ((lane & 3) << 1);
#pragma unroll
    for (int i = 0; i < 4; i++) {
        int m_a = mrow0 + i * 16;
        int m_b = m_a + 8;
#pragma unroll
        for (int j = 0; j < 4; j++) {
            int n = ncol0 + j * 8;
            if (m_a < N_NODES)
                *(float2*)(C + (size_t)m_a * NTOT + n) = make_float2(acc[i][j][0], acc[i][j][1]);
            if (m_b < N_NODES)
                *(float2*)(C + (size_t)m_b * NTOT + n) = make_float2(acc[i][j][2], acc[i][j][3]);
        }
    }
}

// ---------------- aggregate (+bias, +BN, +ReLU): one warp per node ----------
template <int F, bool BNRELU>
__global__ void k_aggregate(const float* __restrict__ xw, float* __restrict__ h,
                            const float* __restrict__ bias,
                            const float* __restrict__ gamma,
                            const float* __restrict__ beta,
                            const float* __restrict__ rm,
                            const float* __restrict__ rv) {
    constexpr int V = F / 128;   // float4 per lane (2 or 3)
    int gw = (int)((blockIdx.x * blockDim.x + threadIdx.x) >> 5);
    if (gw >= N_NODES) return;
    int lane = threadIdx.x & 31;
    int rs = g_rowstart[gw], re = g_rowstart[gw + 1];
    float di = g_dinv[gw];
    const float4* xv = (const float4*)xw;
    size_t rowq = (size_t)gw * (F / 4);
    float self = di * di;
    float4 acc[V];
#pragma unroll
    for (int v = 0; v < V; v++) {
        float4 t = xv[rowq + lane + v * 32];
        acc[v].x = t.x * self; acc[v].y = t.y * self;
        acc[v].z = t.z * self; acc[v].w = t.w * self;
    }
    for (int e0 = rs; e0 < re; e0 += 32) {
        int cnt = min(32, re - e0);
        int sreg = 0; float dreg = 0.0f;
        if (e0 + lane < re) {
            sreg = g_csr[e0 + lane];
            dreg = g_dinv[sreg];
        }
        for (int j = 0; j < cnt; j++) {
            int s = __shfl_sync(0xffffffffu, sreg, j);
            float nrm = __shfl_sync(0xffffffffu, dreg, j) * di;
            size_t sq = (size_t)s * (F / 4);
#pragma unroll
            for (int v = 0; v < V; v++) {
                float4 t = xv[sq + lane + v * 32];
                acc[v].x += t.x * nrm; acc[v].y += t.y * nrm;
                acc[v].z += t.z * nrm; acc[v].w += t.w * nrm;
            }
        }
    }
#pragma unroll
    for (int v = 0; v < V; v++) {
        int c4 = lane + v * 32;
        float4 bb = ((const float4*)bias)[c4];
        float4 o;
        o.x = acc[v].x + bb.x; o.y = acc[v].y + bb.y;
        o.z = acc[v].z + bb.z; o.w = acc[v].w + bb.w;
        if (BNRELU) {
            float4 gm = ((const float4*)gamma)[c4];
            float4 bt = ((const float4*)beta)[c4];
            float4 mm = ((const float4*)rm)[c4];
            float4 vv = ((const float4*)rv)[c4];
            o.x = fmaxf((o.x - mm.x) * rsqrtf(vv.x + 1e-5f) * gm.x + bt.x, 0.0f);
            o.y = fmaxf((o.y - mm.y) * rsqrtf(vv.y + 1e-5f) * gm.y + bt.y, 0.0f);
            o.z = fmaxf((o.z - mm.z) * rsqrtf(vv.z + 1e-5f) * gm.z + bt.z, 0.0f);
            o.w = fmaxf((o.w - mm.w) * rsqrtf(vv.w + 1e-5f) * gm.w + bt.w, 0.0f);
        }
        ((float4*)h)[rowq + c4] = o;
    }
}

// ---------------- pooling: mean + max per graph ----------------------------
__global__ void k_pool(const float* __restrict__ h3, float* __restrict__ out) {
    int g = blockIdx.x;
    int tx = threadIdx.x;
    int s = g_gstart[g], e = g_gstart[g + 1];
    float sum[3] = {0.f, 0.f, 0.f};
    float mx[3]  = {-INFINITY, -INFINITY, -INFINITY};
    for (int n = s; n < e; n++) {
#pragma unroll
        for (int c = 0; c < 3; c++) {
            float v = h3[(size_t)n * 384 + tx + c * 128];
            sum[c] += v;
            mx[c] = fmaxf(mx[c], v);
        }
    }
    float inv = 1.0f / fmaxf((float)(e - s), 1.0f);
#pragma unroll
    for (int c = 0; c < 3; c++)
        out[(size_t)g * 384 + tx + c * 128] = sum[c] * inv + mx[c];
}

// ---------------- launch ----------------------------------------------------
extern "C" void kernel_launch(void* const* d_in, const int* in_sizes, int n_in,
                              void* d_out, int out_size) {
    const float* x     = (const float*)d_in[0];
    const int*   ei    = (const int*)d_in[1];   // [2, E] int32
    const int*   src   = ei;
    const int*   dst   = ei + N_EDGES;
    const int*   batch = (const int*)d_in[2];
    const float* W1 = (const float*)d_in[3];
    const float* b1 = (const float*)d_in[4];
    const float* g1 = (const float*)d_in[5];
    const float* be1 = (const float*)d_in[6];
    const float* rm1 = (const float*)d_in[7];
    const float* rv1 = (const float*)d_in[8];
    const float* W2 = (const float*)d_in[9];
    const float* b2 = (const float*)d_in[10];
    const float* g2 = (const float*)d_in[11];
    const float* be2 = (const float*)d_in[12];
    const float* rm2 = (const float*)d_in[13];
    const float* rv2 = (const float*)d_in[14];
    const float* W3 = (const float*)d_in[15];
    const float* b3 = (const float*)d_in[16];
    float* out = (float*)d_out;

    float *p_buf1, *p_buf2;
    __nv_bfloat16 *p_Aaug, *p_Baug;
    int *p_deg, *p_rowstart, *p_cursor, *p_gcnt, *p_gstart, *p_bsums;
    cudaGetSymbolAddress((void**)&p_buf1, g_buf1);
    cudaGetSymbolAddress((void**)&p_buf2, g_buf2);
    cudaGetSymbolAddress((void**)&p_Aaug, g_Aaug);
    cudaGetSymbolAddress((void**)&p_Baug, g_Baug);
    cudaGetSymbolAddress((void**)&p_deg, g_deg);
    cudaGetSymbolAddress((void**)&p_rowstart, g_rowstart);
    cudaGetSymbolAddress((void**)&p_cursor, g_cursor);
    cudaGetSymbolAddress((void**)&p_gcnt, g_gcnt);
    cudaGetSymbolAddress((void**)&p_gstart, g_gstart);
    cudaGetSymbolAddress((void**)&p_bsums, g_bsums);

    // ---- CSR + pooling segment construction (rebuilt every call) ----
    k_init<<<(N_NODES + 255) / 256, 256>>>();
    k_hist_deg<<<(N_EDGES + 255) / 256, 256>>>(dst);
    k_hist_batch<<<(N_NODES + 255) / 256, 256>>>(batch);

    k_scan_block<<<SCAN_BLOCKS, 1024>>>(p_deg, p_rowstart, N_NODES, p_bsums);
    k_scan_sums<<<1, 128>>>(p_bsums, SCAN_BLOCKS);
    k_scan_add<<<SCAN_BLOCKS, 1024>>>(p_rowstart, N_NODES, p_bsums, N_EDGES, p_cursor);

    k_dinv<<<(N_NODES + 255) / 256, 256>>>();
    k_fill<<<(N_EDGES + 255) / 256, 256>>>(src, dst);

    k_scan_block<<<2, 1024>>>(p_gcnt, p_gstart, N_GRAPHS, p_bsums);
    k_scan_sums<<<1, 128>>>(p_bsums, 2);
    k_scan_add<<<2, 1024>>>(p_gstart, N_GRAPHS, p_bsums, N_NODES, (int*)0);

    const int AGG_BLOCKS = (N_NODES + 7) / 8;   // 8 warps/block

    // ---- Layer 1: x[100000,74] @ W1[74,256], KS=96, K_eff=288 ----
    {
        size_t na = (size_t)MPAD * 96;
        k_convA<<<(int)((na + 255) / 256), 256>>>(x, p_Aaug, N_NODES, 74, 96);
        size_t nb = (size_t)256 * 96;
        k_convB<<<(int)((nb + 255) / 256), 256>>>(W1, p_Baug, 74, 256, 96);
        dim3 grid(256 / 128, MPAD / 128);
        k_gemm_mma<<<grid, 256>>>(p_Aaug, p_Baug, p_buf1, 288, 256);
        k_aggregate<256, true><<<AGG_BLOCKS, 256>>>(p_buf1, p_buf2, b1, g1, be1, rm1, rv1);
    }
    // ---- Layer 2: h1[100000,256] @ W2[256,256], KS=256, K_eff=768 ----
    {
        size_t na = (size_t)MPAD * 256;
        k_convA<<<(int)((na + 255) / 256), 256>>>(p_buf2, p_Aaug, N_NODES, 256, 256);
        size_t nb = (size_t)256 * 256;
        k_convB<<<(int)((nb + 255) / 256), 256>>>(W2, p_Baug, 256, 256, 256);
        dim3 grid(256 / 128, MPAD / 128);
        k_gemm_mma<<<grid, 256>>>(p_Aaug, p_Baug, p_buf1, 768, 256);
        k_aggregate<256, true><<<AGG_BLOCKS, 256>>>(p_buf1, p_buf2, b2, g2, be2, rm2, rv2);
    }
    // ---- Layer 3: h2[100000,256] @ W3[256,384], KS=256, K_eff=768 ----
    {
        size_t na = (size_t)MPAD * 256;
        k_convA<<<(int)((na + 255) / 256), 256>>>(p_buf2, p_Aaug, N_NODES, 256, 256);
        size_t nb = (size_t)384 * 256;
        k_convB<<<(int)((nb + 255) / 256), 256>>>(W3, p_Baug, 256, 384, 256);
        dim3 grid(384 / 128, MPAD / 128);
        k_gemm_mma<<<grid, 256>>>(p_Aaug, p_Baug, p_buf1, 768, 384);
        k_aggregate<384, false><<<AGG_BLOCKS, 256>>>(p_buf1, p_buf2, b3, (const float*)0,
                                                     (const float*)0, (const float*)0,
                                                     (const float*)0);
    }
    // ---- mean+max pool ----
    k_pool<<<N_GRAPHS, 128>>>(p_buf2, out);
}

// round 4
// speedup vs baseline: 2.1712x; 1.6027x over previous
#include <cuda_runtime.h>
#include <cuda_bf16.h>
#include <math.h>
#include <cstdint>

#define N_NODES  100000
#define N_EDGES  1600000
#define N_GRAPHS 2048
#define SCAN_BLOCKS ((N_NODES + 1023) / 1024)   // 98
#define MPAD 100096                              // 782 * 128

// ---------------- scratch (device globals: no allocation allowed) ----------
__device__ float g_buf1[(size_t)N_NODES * 384];            // xpad, later h3
__device__ float g_buf2[(size_t)N_NODES * 384];            // h1, h2
__device__ __nv_bfloat16 g_Aaug[(size_t)MPAD * 768];       // [MPAD, 3*KS]
__device__ __nv_bfloat16 g_Baug[(size_t)384 * 768];        // [NTOT, 3*KS]
__device__ int   g_deg[N_NODES];
__device__ int   g_rowstart[N_NODES + 1];
__device__ int   g_cursor[N_NODES];
__device__ int   g_csr[N_EDGES];
__device__ float g_dinv[N_NODES];
__device__ int   g_gcnt[N_GRAPHS];
__device__ int   g_gstart[N_GRAPHS + 1];
__device__ int   g_bsums[128];

// ======================= low-level helpers ==================================
__device__ __forceinline__ uint32_t smem_u32(const void* p) {
    uint32_t a;
    asm("{ .reg .u64 t; cvta.to.shared.u64 t, %1; cvt.u32.u64 %0, t; }"
        : "=r"(a) : "l"(p));
    return a;
}

__device__ __forceinline__ void cp_async16(uint32_t dst, const void* src) {
    asm volatile("cp.async.cg.shared.global [%0], [%1], 16;"
                 :: "r"(dst), "l"(src));
}
__device__ __forceinline__ void cp_commit() {
    asm volatile("cp.async.commit_group;");
}
__device__ __forceinline__ void cp_wait1() {
    asm volatile("cp.async.wait_group 1;");
}
__device__ __forceinline__ void cp_wait0() {
    asm volatile("cp.async.wait_group 0;");
}

__device__ __forceinline__ void ldsm_x4(uint32_t& r0, uint32_t& r1,
                                        uint32_t& r2, uint32_t& r3, uint32_t addr) {
    asm volatile("ldmatrix.sync.aligned.m8n8.x4.shared.b16 {%0,%1,%2,%3}, [%4];"
                 : "=r"(r0), "=r"(r1), "=r"(r2), "=r"(r3) : "r"(addr));
}

__device__ __forceinline__ void mma16816(float* c, const uint32_t* a, const uint32_t* b) {
    asm volatile(
        "mma.sync.aligned.m16n8k16.row.col.f32.bf16.bf16.f32 "
        "{%0,%1,%2,%3}, {%4,%5,%6,%7}, {%8,%9}, {%0,%1,%2,%3};"
        : "+f"(c[0]), "+f"(c[1]), "+f"(c[2]), "+f"(c[3])
        : "r"(a[0]), "r"(a[1]), "r"(a[2]), "r"(a[3]), "r"(b[0]), "r"(b[1]));
}

__device__ __forceinline__ uint32_t pack_bf2(__nv_bfloat16 a, __nv_bfloat16 b) {
    __nv_bfloat162 t = __halves2bfloat162(a, b);
    return *(uint32_t*)&t;
}

// ---------------- init / histograms ---------------------------------------
__global__ void k_init() {
    int i = blockIdx.x * blockDim.x + threadIdx.x;
    if (i < N_NODES)  g_deg[i] = 0;
    if (i < N_GRAPHS) g_gcnt[i] = 0;
}

__global__ void k_hist_deg(const int* __restrict__ dst) {
    int e = blockIdx.x * blockDim.x + threadIdx.x;
    if (e < N_EDGES) atomicAdd(&g_deg[dst[e]], 1);
}

__global__ void k_hist_batch(const int* __restrict__ batch) {
    int i = blockIdx.x * blockDim.x + threadIdx.x;
    if (i < N_NODES) atomicAdd(&g_gcnt[batch[i]], 1);
}

// ---------------- generic exclusive scan (3 kernels) -----------------------
__global__ void k_scan_block(const int* __restrict__ in, int* __restrict__ out,
                             int n, int* __restrict__ bsums) {
    __shared__ int sm[1024];
    int i = blockIdx.x * 1024 + threadIdx.x;
    int v = (i < n) ? in[i] : 0;
    sm[threadIdx.x] = v;
    __syncthreads();
    for (int off = 1; off < 1024; off <<= 1) {
        int t = (threadIdx.x >= off) ? sm[threadIdx.x - off] : 0;
        __syncthreads();
        sm[threadIdx.x] += t;
        __syncthreads();
    }
    if (i < n) out[i] = sm[threadIdx.x] - v;           // exclusive
    if (threadIdx.x == 1023) bsums[blockIdx.x] = sm[1023];
}

__global__ void k_scan_sums(int* __restrict__ bsums, int nb) {  // 1 block, 128 thr
    __shared__ int sm[128];
    int v = (threadIdx.x < nb) ? bsums[threadIdx.x] : 0;
    sm[threadIdx.x] = v;
    __syncthreads();
    for (int off = 1; off < 128; off <<= 1) {
        int t = (threadIdx.x >= off) ? sm[threadIdx.x - off] : 0;
        __syncthreads();
        sm[threadIdx.x] += t;
        __syncthreads();
    }
    if (threadIdx.x < nb) bsums[threadIdx.x] = sm[threadIdx.x] - v;  // exclusive
}

__global__ void k_scan_add(int* __restrict__ out, int n,
                           const int* __restrict__ bsums, int total,
                           int* __restrict__ cursor) {
    int i = blockIdx.x * 1024 + threadIdx.x;
    if (i < n) {
        int v = out[i] + bsums[blockIdx.x];
        out[i] = v;
        if (cursor) cursor[i] = v;
    }
    if (i == 0) out[n] = total;
}

// ---------------- dinv + CSR fill ------------------------------------------
__global__ void k_dinv() {
    int i = blockIdx.x * blockDim.x + threadIdx.x;
    if (i < N_NODES) g_dinv[i] = rsqrtf((float)g_deg[i] + 1.0f);
}

__global__ void k_fill(const int* __restrict__ src, const int* __restrict__ dst) {
    int e = blockIdx.x * blockDim.x + threadIdx.x;
    if (e < N_EDGES) {
        int d = dst[e];
        int p = atomicAdd(&g_cursor[d], 1);
        g_csr[p] = src[e];
    }
}

// ---------------- pad x [N,74] -> xpad [N,96] -------------------------------
__global__ void k_padx(const float* __restrict__ x, float* __restrict__ xp) {
    size_t idx = (size_t)blockIdx.x * blockDim.x + threadIdx.x;
    if (idx >= (size_t)N_NODES * 96) return;
    int r = (int)(idx / 96), k = (int)(idx % 96);
    xp[idx] = (k < 74) ? x[(size_t)r * 74 + k] : 0.0f;
}

// ---------------- B: W [K,N] fp32 -> Baug [NTOT, 3*KS] bf16 (hi|hi|lo) ------
__global__ void k_convB(const float* __restrict__ W,
                        __nv_bfloat16* __restrict__ Baug,
                        int Kreal, int N, int KS) {
    size_t idx = (size_t)blockIdx.x * blockDim.x + threadIdx.x;
    size_t total = (size_t)N * KS;
    if (idx >= total) return;
    int n = (int)(idx / KS);
    int k = (int)(idx % KS);
    float v = (k < Kreal) ? W[(size_t)k * N + n] : 0.0f;
    __nv_bfloat16 h = __float2bfloat16(v);
    __nv_bfloat16 l = __float2bfloat16(v - __bfloat162float(h));
    size_t base = (size_t)n * (3 * KS) + k;
    Baug[base]          = h;
    Baug[base + KS]     = h;
    Baug[base + 2 * KS] = l;
}

// ---------------- aggregate-first: one warp per node -------------------------
// Aaug[row, 0:F)=hi(agg), [F,2F)=lo(agg), [2F,3F)=hi(agg)
template <int F>
__global__ void k_agg_pre(const float* __restrict__ hin,
                          __nv_bfloat16* __restrict__ Aaug) {
    constexpr int Q  = F / 4;             // float4 per row
    constexpr int NV = (Q + 31) / 32;
    int gw = (int)((blockIdx.x * blockDim.x + threadIdx.x) >> 5);
    if (gw >= N_NODES) return;
    int lane = threadIdx.x & 31;
    int rs = g_rowstart[gw], re = g_rowstart[gw + 1];
    float di = g_dinv[gw];
    const float4* xv = (const float4*)hin;
    size_t rowq = (size_t)gw * Q;
    float self = di * di;
    float4 acc[NV];
    bool act[NV];
#pragma unroll
    for (int v = 0; v < NV; v++) {
        act[v] = (lane + v * 32) < Q;
        if (act[v]) {
            float4 t = xv[rowq + lane + v * 32];
            acc[v].x = t.x * self; acc[v].y = t.y * self;
            acc[v].z = t.z * self; acc[v].w = t.w * self;
        }
    }
    for (int e0 = rs; e0 < re; e0 += 32) {
        int cnt = min(32, re - e0);
        int sreg = 0; float dreg = 0.0f;
        if (e0 + lane < re) {
            sreg = g_csr[e0 + lane];
            dreg = g_dinv[sreg];
        }
        for (int j = 0; j < cnt; j++) {
            int s = __shfl_sync(0xffffffffu, sreg, j);
            float nrm = __shfl_sync(0xffffffffu, dreg, j) * di;
            size_t sq = (size_t)s * Q;
#pragma unroll
            for (int v = 0; v < NV; v++) {
                if (act[v]) {
                    float4 t = xv[sq + lane + v * 32];
                    acc[v].x += t.x * nrm; acc[v].y += t.y * nrm;
                    acc[v].z += t.z * nrm; acc[v].w += t.w * nrm;
                }
            }
        }
    }
    // ---- emit bf16 hi/lo/hi augmented row directly ----
    size_t obase = (size_t)gw * (3 * F);
#pragma unroll
    for (int v = 0; v < NV; v++) {
        if (!act[v]) continue;
        int c0 = 4 * (lane + v * 32);
        __nv_bfloat16 h0 = __float2bfloat16(acc[v].x);
        __nv_bfloat16 h1 = __float2bfloat16(acc[v].y);
        __nv_bfloat16 h2 = __float2bfloat16(acc[v].z);
        __nv_bfloat16 h3 = __float2bfloat16(acc[v].w);
        __nv_bfloat16 l0 = __float2bfloat16(acc[v].x - __bfloat162float(h0));
        __nv_bfloat16 l1 = __float2bfloat16(acc[v].y - __bfloat162float(h1));
        __nv_bfloat16 l2 = __float2bfloat16(acc[v].z - __bfloat162float(h2));
        __nv_bfloat16 l3 = __float2bfloat16(acc[v].w - __bfloat162float(h3));
        uint2 hi, lo;
        hi.x = pack_bf2(h0, h1); hi.y = pack_bf2(h2, h3);
        lo.x = pack_bf2(l0, l1); lo.y = pack_bf2(l2, l3);
        *(uint2*)(Aaug + obase + c0)         = hi;
        *(uint2*)(Aaug + obase + F + c0)     = lo;
        *(uint2*)(Aaug + obase + 2 * F + c0) = hi;
    }
}

// ---------------- bf16 mma.sync GEMM + fused epilogue ------------------------
// C[m,n] = sum_k Aaug[m,k] * Baug[n,k] ; then EPI: bias (+BN+ReLU)
#define GS 40   // smem row stride in bf16 (32 data + 8 pad = 80B, conflict-free)

template <int EPI>   // 0 = +bias, 1 = +bias,BN,ReLU
__global__ __launch_bounds__(256, 2)
void k_gemm_mma(const __nv_bfloat16* __restrict__ A,
                const __nv_bfloat16* __restrict__ B,
                float* __restrict__ C, int K, int NTOT,
                const float* __restrict__ bias,
                const float* __restrict__ gamma,
                const float* __restrict__ beta,
                const float* __restrict__ rm,
                const float* __restrict__ rv) {
    __shared__ __align__(16) __nv_bfloat16 As[2][128 * GS];
    __shared__ __align__(16) __nv_bfloat16 Bs[2][128 * GS];

    int tid = threadIdx.x;
    int wid = tid >> 5, lane = tid & 31;
    int warp_m = wid & 1;          // 2 warps along M (64 rows each)
    int warp_n = wid >> 1;         // 4 warps along N (32 cols each)
    int rowBase = blockIdx.y * 128;
    int colBase = blockIdx.x * 128;

    uint32_t asb = smem_u32(&As[0][0]);
    uint32_t bsb = smem_u32(&Bs[0][0]);
    const uint32_t bufBytes = 128 * GS * 2;

    float acc[4][4][4];
#pragma unroll
    for (int i = 0; i < 4; i++)
#pragma unroll
        for (int j = 0; j < 4; j++)
#pragma unroll
            for (int q = 0; q < 4; q++) acc[i][j][q] = 0.0f;

    const int NC = K >> 5;   // 32-wide K chunks

    auto load_chunk = [&](int c, int buf) {
        int k0 = c << 5;
#pragma unroll
        for (int t = 0; t < 2; t++) {
            int idx = tid + (t << 8);             // 0..511
            int r = idx >> 2, seg = idx & 3;      // row 0..127, 16B segment 0..3
            uint32_t doff = (uint32_t)(r * GS + seg * 8) * 2;
            cp_async16(asb + buf * bufBytes + doff,
                       A + (size_t)(rowBase + r) * K + k0 + seg * 8);
            cp_async16(bsb + buf * bufBytes + doff,
                       B + (size_t)(colBase + r) * K + k0 + seg * 8);
        }
        cp_commit();
    };

    load_chunk(0, 0);

    for (int c = 0; c < NC; c++) {
        int buf = c & 1;
        if (c + 1 < NC) {
            load_chunk(c + 1, buf ^ 1);
            cp_wait1();
        } else {
            cp_wait0();
        }
        __syncthreads();

        uint32_t aBase = asb + buf * bufBytes;
        uint32_t bBase = bsb + buf * bufBytes;
#pragma unroll
        for (int kk = 0; kk < 2; kk++) {
            uint32_t af[4][4];
            {
                int row = warp_m * 64 + (lane & 15);
                int kcol = kk * 16 + ((lane >> 4) << 3);
#pragma unroll
                for (int i = 0; i < 4; i++) {
                    uint32_t addr = aBase + (uint32_t)((row + i * 16) * GS + kcol) * 2;
                    ldsm_x4(af[i][0], af[i][1], af[i][2], af[i][3], addr);
                }
            }
            uint32_t bf[4][2];
            {
                int rown = warp_n * 32 + (lane & 7) + ((lane & 16) ? 8 : 0);
                int kcol = kk * 16 + ((lane & 8) ? 8 : 0);
#pragma unroll
                for (int jj = 0; jj < 2; jj++) {
                    uint32_t addr = bBase + (uint32_t)((rown + jj * 16) * GS + kcol) * 2;
                    ldsm_x4(bf[jj * 2][0], bf[jj * 2][1],
                            bf[jj * 2 + 1][0], bf[jj * 2 + 1][1], addr);
                }
            }
#pragma unroll
            for (int i = 0; i < 4; i++)
#pragma unroll
                for (int j = 0; j < 4; j++)
                    mma16816(acc[i][j], af[i], bf[j]);
        }
        __syncthreads();
    }

    // ---- epilogue: bias (+BN+ReLU), store fp32 ----
    int mrow0 = rowBase + warp_m * 64 + (lane >> 2);
    int ncol0 = colBase + warp_n * 32 + ((lane & 3) << 1);
#pragma unroll
    for (int j = 0; j < 4; j++) {
        int n = ncol0 + j * 8;
        float b0 = bias[n], b1 = bias[n + 1];
        float s0 = 0.f, s1 = 0.f, t0 = 0.f, t1 = 0.f, m0 = 0.f, m1 = 0.f;
        if (EPI) {
            s0 = gamma[n]     * rsqrtf(rv[n]     + 1e-5f);
            s1 = gamma[n + 1] * rsqrtf(rv[n + 1] + 1e-5f);
            t0 = beta[n];  t1 = beta[n + 1];
            m0 = rm[n];    m1 = rm[n + 1];
        }
#pragma unroll
        for (int i = 0; i < 4; i++) {
            int m_a = mrow0 + i * 16;
            int m_b = m_a + 8;
            float v0 = acc[i][j][0] + b0, v1 = acc[i][j][1] + b1;
            float v2 = acc[i][j][2] + b0, v3 = acc[i][j][3] + b1;
            if (EPI) {
                v0 = fmaxf((v0 - m0) * s0 + t0, 0.0f);
                v1 = fmaxf((v1 - m1) * s1 + t1, 0.0f);
                v2 = fmaxf((v2 - m0) * s0 + t0, 0.0f);
                v3 = fmaxf((v3 - m1) * s1 + t1, 0.0f);
            }
            if (m_a < N_NODES)
                *(float2*)(C + (size_t)m_a * NTOT + n) = make_float2(v0, v1);
            if (m_b < N_NODES)
                *(float2*)(C + (size_t)m_b * NTOT + n) = make_float2(v2, v3);
        }
    }
}

// ---------------- pooling: mean + max per graph ----------------------------
__global__ void k_pool(const float* __restrict__ h3, float* __restrict__ out) {
    int g = blockIdx.x;
    int tx = threadIdx.x;
    int s = g_gstart[g], e = g_gstart[g + 1];
    float sum[3] = {0.f, 0.f, 0.f};
    float mx[3]  = {-INFINITY, -INFINITY, -INFINITY};
    for (int n = s; n < e; n++) {
#pragma unroll
        for (int c = 0; c < 3; c++) {
            float v = h3[(size_t)n * 384 + tx + c * 128];
            sum[c] += v;
            mx[c] = fmaxf(mx[c], v);
        }
    }
    float inv = 1.0f / fmaxf((float)(e - s), 1.0f);
#pragma unroll
    for (int c = 0; c < 3; c++)
        out[(size_t)g * 384 + tx + c * 128] = sum[c] * inv + mx[c];
}

// ---------------- launch ----------------------------------------------------
extern "C" void kernel_launch(void* const* d_in, const int* in_sizes, int n_in,
                              void* d_out, int out_size) {
    const float* x     = (const float*)d_in[0];
    const int*   ei    = (const int*)d_in[1];   // [2, E] int32
    const int*   src   = ei;
    const int*   dst   = ei + N_EDGES;
    const int*   batch = (const int*)d_in[2];
    const float* W1 = (const float*)d_in[3];
    const float* b1 = (const float*)d_in[4];
    const float* g1 = (const float*)d_in[5];
    const float* be1 = (const float*)d_in[6];
    const float* rm1 = (const float*)d_in[7];
    const float* rv1 = (const float*)d_in[8];
    const float* W2 = (const float*)d_in[9];
    const float* b2 = (const float*)d_in[10];
    const float* g2 = (const float*)d_in[11];
    const float* be2 = (const float*)d_in[12];
    const float* rm2 = (const float*)d_in[13];
    const float* rv2 = (const float*)d_in[14];
    const float* W3 = (const float*)d_in[15];
    const float* b3 = (const float*)d_in[16];
    float* out = (float*)d_out;

    float *p_buf1, *p_buf2;
    __nv_bfloat16 *p_Aaug, *p_Baug;
    int *p_deg, *p_rowstart, *p_cursor, *p_gcnt, *p_gstart, *p_bsums;
    cudaGetSymbolAddress((void**)&p_buf1, g_buf1);
    cudaGetSymbolAddress((void**)&p_buf2, g_buf2);
    cudaGetSymbolAddress((void**)&p_Aaug, g_Aaug);
    cudaGetSymbolAddress((void**)&p_Baug, g_Baug);
    cudaGetSymbolAddress((void**)&p_deg, g_deg);
    cudaGetSymbolAddress((void**)&p_rowstart, g_rowstart);
    cudaGetSymbolAddress((void**)&p_cursor, g_cursor);
    cudaGetSymbolAddress((void**)&p_gcnt, g_gcnt);
    cudaGetSymbolAddress((void**)&p_gstart, g_gstart);
    cudaGetSymbolAddress((void**)&p_bsums, g_bsums);

    // ---- CSR + pooling segment construction (rebuilt every call) ----
    k_init<<<(N_NODES + 255) / 256, 256>>>();
    k_hist_deg<<<(N_EDGES + 255) / 256, 256>>>(dst);
    k_hist_batch<<<(N_NODES + 255) / 256, 256>>>(batch);

    k_scan_block<<<SCAN_BLOCKS, 1024>>>(p_deg, p_rowstart, N_NODES, p_bsums);
    k_scan_sums<<<1, 128>>>(p_bsums, SCAN_BLOCKS);
    k_scan_add<<<SCAN_BLOCKS, 1024>>>(p_rowstart, N_NODES, p_bsums, N_EDGES, p_cursor);

    k_dinv<<<(N_NODES + 255) / 256, 256>>>();
    k_fill<<<(N_EDGES + 255) / 256, 256>>>(src, dst);

    k_scan_block<<<2, 1024>>>(p_gcnt, p_gstart, N_GRAPHS, p_bsums);
    k_scan_sums<<<1, 128>>>(p_bsums, 2);
    k_scan_add<<<2, 1024>>>(p_gstart, N_GRAPHS, p_bsums, N_NODES, (int*)0);

    const int AGG_BLOCKS = (N_NODES + 7) / 8;   // 8 warps/block

    // ---- Layer 1: agg(xpad)[100k,96] @ W1 -> BN+ReLU -> h1(buf2) ----
    {
        size_t np = (size_t)N_NODES * 96;
        k_padx<<<(int)((np + 255) / 256), 256>>>(x, p_buf1);
        size_t nb = (size_t)256 * 96;
        k_convB<<<(int)((nb + 255) / 256), 256>>>(W1, p_Baug, 74, 256, 96);
        k_agg_pre<96><<<AGG_BLOCKS, 256>>>(p_buf1, p_Aaug);
        dim3 grid(256 / 128, MPAD / 128);
        k_gemm_mma<1><<<grid, 256>>>(p_Aaug, p_Baug, p_buf2, 288, 256,
                                     b1, g1, be1, rm1, rv1);
    }
    // ---- Layer 2: agg(h1) @ W2 -> BN+ReLU -> h2(buf2) ----
    {
        size_t nb = (size_t)256 * 256;
        k_convB<<<(int)((nb + 255) / 256), 256>>>(W2, p_Baug, 256, 256, 256);
        k_agg_pre<256><<<AGG_BLOCKS, 256>>>(p_buf2, p_Aaug);
        dim3 grid(256 / 128, MPAD / 128);
        k_gemm_mma<1><<<grid, 256>>>(p_Aaug, p_Baug, p_buf2, 768, 256,
                                     b2, g2, be2, rm2, rv2);
    }
    // ---- Layer 3: agg(h2) @ W3 -> +b3 -> h3(buf1) ----
    {
        size_t nb = (size_t)384 * 256;
        k_convB<<<(int)((nb + 255) / 256), 256>>>(W3, p_Baug, 256, 384, 256);
        k_agg_pre<256><<<AGG_BLOCKS, 256>>>(p_buf2, p_Aaug);
        dim3 grid(384 / 128, MPAD / 128);
        k_gemm_mma<0><<<grid, 256>>>(p_Aaug, p_Baug, p_buf1, 768, 384,
                                     b3, (const float*)0, (const float*)0,
                                     (const float*)0, (const float*)0);
    }
    // ---- mean+max pool ----
    k_pool<<<N_GRAPHS, 128>>>(p_buf1, out);
}

// round 5
// speedup vs baseline: 2.6985x; 1.2429x over previous
#include <cuda_runtime.h>
#include <cuda_fp16.h>
#include <math.h>
#include <cstdint>

#define N_NODES  100000
#define N_EDGES  1600000
#define N_GRAPHS 2048
#define SCAN_BLOCKS ((N_NODES + 1023) / 1024)   // 98
#define MPAD 100096                              // 782 * 128

// ---------------- scratch (device globals: no allocation allowed) ----------
__device__ float g_buf1[(size_t)N_NODES * 384];            // h3
__device__ float g_buf2[(size_t)N_NODES * 384];            // h1, h2
__device__ __half g_Aaug[(size_t)MPAD * 512];              // [MPAD, 2*KS]
__device__ __half g_Baug[(size_t)384 * 512];               // [NTOT, 2*KS]
__device__ int   g_deg[N_NODES];
__device__ int   g_rowstart[N_NODES + 1];
__device__ int   g_cursor[N_NODES];
__device__ int   g_csr[N_EDGES];
__device__ float g_dinv[N_NODES];
__device__ int   g_gcnt[N_GRAPHS];
__device__ int   g_gstart[N_GRAPHS + 1];
__device__ int   g_bsums[128];

// ======================= low-level helpers ==================================
__device__ __forceinline__ uint32_t smem_u32(const void* p) {
    uint32_t a;
    asm("{ .reg .u64 t; cvta.to.shared.u64 t, %1; cvt.u32.u64 %0, t; }"
        : "=r"(a) : "l"(p));
    return a;
}

__device__ __forceinline__ void cp_async16(uint32_t dst, const void* src) {
    asm volatile("cp.async.cg.shared.global [%0], [%1], 16;"
                 :: "r"(dst), "l"(src));
}
__device__ __forceinline__ void cp_commit() {
    asm volatile("cp.async.commit_group;");
}
__device__ __forceinline__ void cp_wait1() {
    asm volatile("cp.async.wait_group 1;");
}
__device__ __forceinline__ void cp_wait0() {
    asm volatile("cp.async.wait_group 0;");
}

__device__ __forceinline__ void ldsm_x4(uint32_t& r0, uint32_t& r1,
                                        uint32_t& r2, uint32_t& r3, uint32_t addr) {
    asm volatile("ldmatrix.sync.aligned.m8n8.x4.shared.b16 {%0,%1,%2,%3}, [%4];"
                 : "=r"(r0), "=r"(r1), "=r"(r2), "=r"(r3) : "r"(addr));
}

__device__ __forceinline__ void mma16816(float* c, const uint32_t* a, const uint32_t* b) {
    asm volatile(
        "mma.sync.aligned.m16n8k16.row.col.f32.f16.f16.f32 "
        "{%0,%1,%2,%3}, {%4,%5,%6,%7}, {%8,%9}, {%0,%1,%2,%3};"
        : "+f"(c[0]), "+f"(c[1]), "+f"(c[2]), "+f"(c[3])
        : "r"(a[0]), "r"(a[1]), "r"(a[2]), "r"(a[3]), "r"(b[0]), "r"(b[1]));
}

__device__ __forceinline__ uint32_t pack_hf2(__half a, __half b) {
    __half2 t = __halves2half2(a, b);
    return *(uint32_t*)&t;
}

// ---------------- fused histogram: deg (edges) + gcnt (nodes) ---------------
__global__ void k_hist(const int* __restrict__ dst, const int* __restrict__ batch) {
    int i = blockIdx.x * blockDim.x + threadIdx.x;
    if (i < N_EDGES) atomicAdd(&g_deg[dst[i]], 1);
    if (i < N_NODES) atomicAdd(&g_gcnt[batch[i]], 1);
}

// ---------------- exclusive scan over deg (3 kernels, dinv fused) -----------
__global__ void k_scan_block(const int* __restrict__ in, int* __restrict__ out,
                             int n, int* __restrict__ bsums) {
    __shared__ int sm[1024];
    int i = blockIdx.x * 1024 + threadIdx.x;
    int v = (i < n) ? in[i] : 0;
    sm[threadIdx.x] = v;
    __syncthreads();
    for (int off = 1; off < 1024; off <<= 1) {
        int t = (threadIdx.x >= off) ? sm[threadIdx.x - off] : 0;
        __syncthreads();
        sm[threadIdx.x] += t;
        __syncthreads();
    }
    if (i < n) out[i] = sm[threadIdx.x] - v;           // exclusive
    if (threadIdx.x == 1023) bsums[blockIdx.x] = sm[1023];
}

__global__ void k_scan_sums(int* __restrict__ bsums, int nb) {  // 1 block, 128 thr
    __shared__ int sm[128];
    int v = (threadIdx.x < nb) ? bsums[threadIdx.x] : 0;
    sm[threadIdx.x] = v;
    __syncthreads();
    for (int off = 1; off < 128; off <<= 1) {
        int t = (threadIdx.x >= off) ? sm[threadIdx.x - off] : 0;
        __syncthreads();
        sm[threadIdx.x] += t;
        __syncthreads();
    }
    if (threadIdx.x < nb) bsums[threadIdx.x] = sm[threadIdx.x] - v;  // exclusive
}

// rowstart += block offset; also cursor copy + dinv (deg still in g_deg)
__global__ void k_scan_add(int* __restrict__ out, int n,
                           const int* __restrict__ bsums, int total,
                           int* __restrict__ cursor) {
    int i = blockIdx.x * 1024 + threadIdx.x;
    if (i < n) {
        int v = out[i] + bsums[blockIdx.x];
        out[i] = v;
        cursor[i] = v;
        g_dinv[i] = rsqrtf((float)g_deg[i] + 1.0f);
    }
    if (i == 0) out[n] = total;
}

__global__ void k_fill(const int* __restrict__ src, const int* __restrict__ dst) {
    int e = blockIdx.x * blockDim.x + threadIdx.x;
    if (e < N_EDGES) {
        int d = dst[e];
        int p = atomicAdd(&g_cursor[d], 1);
        g_csr[p] = src[e];
    }
}

// ---------------- single-block scan for graph segments (2048 bins) ----------
__global__ void k_scan_graphs() {
    __shared__ int sm[2048];
    int t = threadIdx.x;
    int v0 = g_gcnt[t], v1 = g_gcnt[t + 1024];
    sm[t] = v0; sm[t + 1024] = v1;
    __syncthreads();
    for (int off = 1; off < 2048; off <<= 1) {
        int i1 = t + 1024;
        int t0 = (t >= off) ? sm[t - off] : 0;
        int t1 = (i1 >= off) ? sm[i1 - off] : 0;
        __syncthreads();
        sm[t] += t0; sm[i1] += t1;
        __syncthreads();
    }
    g_gstart[t] = sm[t] - v0;
    g_gstart[t + 1024] = sm[t + 1024] - v1;
    if (t == 0) g_gstart[2048] = N_NODES;
}

// ---------------- B: W [K,N] fp32 -> Baug [N, 2*KS] fp16 (hi|hi) ------------
__global__ void k_convB(const float* __restrict__ W,
                        __half* __restrict__ Baug,
                        int Kreal, int N, int KS) {
    size_t idx = (size_t)blockIdx.x * blockDim.x + threadIdx.x;
    size_t total = (size_t)N * KS;
    if (idx >= total) return;
    int n = (int)(idx / KS);
    int k = (int)(idx % KS);
    float v = (k < Kreal) ? W[(size_t)k * N + n] : 0.0f;
    __half h = __float2half_rn(v);
    size_t base = (size_t)n * (2 * KS) + k;
    Baug[base]      = h;
    Baug[base + KS] = h;
}

// ---------------- layer-1 aggregate: x [N,74] -> Aaug [N, 160] (hi|lo) ------
__global__ void k_agg_pre74(const float* __restrict__ x,
                            __half* __restrict__ Aaug) {
    int gw = (int)((blockIdx.x * blockDim.x + threadIdx.x) >> 5);
    if (gw >= N_NODES) return;
    int lane = threadIdx.x & 31;
    int rs = g_rowstart[gw], re = g_rowstart[gw + 1];
    float di = g_dinv[gw];
    float self = di * di;
    const float* row = x + (size_t)gw * 74;
    float a0 = row[lane] * self;
    float a1 = row[lane + 32] * self;
    float a2 = (lane < 10) ? row[lane + 64] * self : 0.0f;
    for (int e0 = rs; e0 < re; e0 += 32) {
        int cnt = min(32, re - e0);
        int sreg = 0; float dreg = 0.0f;
        if (e0 + lane < re) {
            sreg = g_csr[e0 + lane];
            dreg = g_dinv[sreg];
        }
        for (int j = 0; j < cnt; j++) {
            int s = __shfl_sync(0xffffffffu, sreg, j);
            float nrm = __shfl_sync(0xffffffffu, dreg, j) * di;
            const float* sr = x + (size_t)s * 74;
            a0 += sr[lane] * nrm;
            a1 += sr[lane + 32] * nrm;
            if (lane < 10) a2 += sr[lane + 64] * nrm;
        }
    }
    // emit hi at col, lo at col+80 (row width 160), cols 74..79 zero
    size_t base = (size_t)gw * 160;
    {
        __half h = __float2half_rn(a0);
        __half l = __float2half_rn(a0 - __half2float(h));
        Aaug[base + lane] = h; Aaug[base + 80 + lane] = l;
    }
    {
        __half h = __float2half_rn(a1);
        __half l = __float2half_rn(a1 - __half2float(h));
        Aaug[base + lane + 32] = h; Aaug[base + 80 + lane + 32] = l;
    }
    if (lane < 16) {   // cols 64..79; lanes 10..15 emit zeros (a2 stays 0)
        __half h = __float2half_rn(a2);
        __half l = __float2half_rn(a2 - __half2float(h));
        Aaug[base + lane + 64] = h; Aaug[base + 80 + lane + 64] = l;
    }
}

// ---------------- aggregate (F=256): one warp per node -> Aaug [N,512] ------
__global__ void k_agg_pre256(const float* __restrict__ hin,
                             __half* __restrict__ Aaug) {
    int gw = (int)((blockIdx.x * blockDim.x + threadIdx.x) >> 5);
    if (gw >= N_NODES) return;
    int lane = threadIdx.x & 31;
    int rs = g_rowstart[gw], re = g_rowstart[gw + 1];
    float di = g_dinv[gw];
    const float4* xv = (const float4*)hin;
    size_t rowq = (size_t)gw * 64;
    float self = di * di;
    float4 acc[2];
#pragma unroll
    for (int v = 0; v < 2; v++) {
        float4 t = xv[rowq + lane + v * 32];
        acc[v].x = t.x * self; acc[v].y = t.y * self;
        acc[v].z = t.z * self; acc[v].w = t.w * self;
    }
    for (int e0 = rs; e0 < re; e0 += 32) {
        int cnt = min(32, re - e0);
        int sreg = 0; float dreg = 0.0f;
        if (e0 + lane < re) {
            sreg = g_csr[e0 + lane];
            dreg = g_dinv[sreg];
        }
        for (int j = 0; j < cnt; j++) {
            int s = __shfl_sync(0xffffffffu, sreg, j);
            float nrm = __shfl_sync(0xffffffffu, dreg, j) * di;
            size_t sq = (size_t)s * 64;
#pragma unroll
            for (int v = 0; v < 2; v++) {
                float4 t = xv[sq + lane + v * 32];
                acc[v].x += t.x * nrm; acc[v].y += t.y * nrm;
                acc[v].z += t.z * nrm; acc[v].w += t.w * nrm;
            }
        }
    }
    size_t obase = (size_t)gw * 512;
#pragma unroll
    for (int v = 0; v < 2; v++) {
        int c0 = 4 * (lane + v * 32);
        __half h0 = __float2half_rn(acc[v].x);
        __half h1 = __float2half_rn(acc[v].y);
        __half h2 = __float2half_rn(acc[v].z);
        __half h3 = __float2half_rn(acc[v].w);
        __half l0 = __float2half_rn(acc[v].x - __half2float(h0));
        __half l1 = __float2half_rn(acc[v].y - __half2float(h1));
        __half l2 = __float2half_rn(acc[v].z - __half2float(h2));
        __half l3 = __float2half_rn(acc[v].w - __half2float(h3));
        uint2 hi, lo;
        hi.x = pack_hf2(h0, h1); hi.y = pack_hf2(h2, h3);
        lo.x = pack_hf2(l0, l1); lo.y = pack_hf2(l2, l3);
        *(uint2*)(g_Aaug + obase + c0)       = hi;
        *(uint2*)(g_Aaug + obase + 256 + c0) = lo;
    }
    (void)Aaug;
}

// ---------------- fp16 mma.sync GEMM + fused epilogue ------------------------
// C[m,n] = sum_k Aaug[m,k] * Baug[n,k] ; EPI: 0 = +bias, 1 = +bias,BN,ReLU
#define GS 40   // smem row stride in halves (32 data + 8 pad = 80B, conflict-free)

template <int EPI>
__global__ __launch_bounds__(256, 2)
void k_gemm_mma(const __half* __restrict__ A,
                const __half* __restrict__ B,
                float* __restrict__ C, int K, int NTOT,
                const float* __restrict__ bias,
                const float* __restrict__ gamma,
                const float* __restrict__ beta,
                const float* __restrict__ rm,
                const float* __restrict__ rv) {
    __shared__ __align__(16) __half As[2][128 * GS];
    __shared__ __align__(16) __half Bs[2][128 * GS];

    int tid = threadIdx.x;
    int wid = tid >> 5, lane = tid & 31;
    int warp_m = wid & 1;
    int warp_n = wid >> 1;
    int rowBase = blockIdx.y * 128;
    int colBase = blockIdx.x * 128;

    uint32_t asb = smem_u32(&As[0][0]);
    uint32_t bsb = smem_u32(&Bs[0][0]);
    const uint32_t bufBytes = 128 * GS * 2;

    float acc[4][4][4];
#pragma unroll
    for (int i = 0; i < 4; i++)
#pragma unroll
        for (int j = 0; j < 4; j++)
#pragma unroll
            for (int q = 0; q < 4; q++) acc[i][j][q] = 0.0f;

    const int NC = K >> 5;

    auto load_chunk = [&](int c, int buf) {
        int k0 = c << 5;
#pragma unroll
        for (int t = 0; t < 2; t++) {
            int idx = tid + (t << 8);
            int r = idx >> 2, seg = idx & 3;
            uint32_t doff = (uint32_t)(r * GS + seg * 8) * 2;
            cp_async16(asb + buf * bufBytes + doff,
                       A + (size_t)(rowBase + r) * K + k0 + seg * 8);
            cp_async16(bsb + buf * bufBytes + doff,
                       B + (size_t)(colBase + r) * K + k0 + seg * 8);
        }
        cp_commit();
    };

    load_chunk(0, 0);

    for (int c = 0; c < NC; c++) {
        int buf = c & 1;
        if (c + 1 < NC) {
            load_chunk(c + 1, buf ^ 1);
            cp_wait1();
        } else {
            cp_wait0();
        }
        __syncthreads();

        uint32_t aBase = asb + buf * bufBytes;
        uint32_t bBase = bsb + buf * bufBytes;
#pragma unroll
        for (int kk = 0; kk < 2; kk++) {
            uint32_t af[4][4];
            {
                int row = warp_m * 64 + (lane & 15);
                int kcol = kk * 16 + ((lane >> 4) << 3);
#pragma unroll
                for (int i = 0; i < 4; i++) {
                    uint32_t addr = aBase + (uint32_t)((row + i * 16) * GS + kcol) * 2;
                    ldsm_x4(af[i][0], af[i][1], af[i][2], af[i][3], addr);
                }
            }
            uint32_t bf[4][2];
            {
                int rown = warp_n * 32 + (lane & 7) + ((lane & 16) ? 8 : 0);
                int kcol = kk * 16 + ((lane & 8) ? 8 : 0);
#pragma unroll
                for (int jj = 0; jj < 2; jj++) {
                    uint32_t addr = bBase + (uint32_t)((rown + jj * 16) * GS + kcol) * 2;
                    ldsm_x4(bf[jj * 2][0], bf[jj * 2][1],
                            bf[jj * 2 + 1][0], bf[jj * 2 + 1][1], addr);
                }
            }
#pragma unroll
            for (int i = 0; i < 4; i++)
#pragma unroll
                for (int j = 0; j < 4; j++)
                    mma16816(acc[i][j], af[i], bf[j]);
        }
        __syncthreads();
    }

    int mrow0 = rowBase + warp_m * 64 + (lane >> 2);
    int ncol0 = colBase + warp_n * 32 + ((lane & 3) << 1);
#pragma unroll
    for (int j = 0; j < 4; j++) {
        int n = ncol0 + j * 8;
        float b0 = bias[n], b1 = bias[n + 1];
        float s0 = 0.f, s1 = 0.f, t0 = 0.f, t1 = 0.f, m0 = 0.f, m1 = 0.f;
        if (EPI) {
            s0 = gamma[n]     * rsqrtf(rv[n]     + 1e-5f);
            s1 = gamma[n + 1] * rsqrtf(rv[n + 1] + 1e-5f);
            t0 = beta[n];  t1 = beta[n + 1];
            m0 = rm[n];    m1 = rm[n + 1];
        }
#pragma unroll
        for (int i = 0; i < 4; i++) {
            int m_a = mrow0 + i * 16;
            int m_b = m_a + 8;
            float v0 = acc[i][j][0] + b0, v1 = acc[i][j][1] + b1;
            float v2 = acc[i][j][2] + b0, v3 = acc[i][j][3] + b1;
            if (EPI) {
                v0 = fmaxf((v0 - m0) * s0 + t0, 0.0f);
                v1 = fmaxf((v1 - m1) * s1 + t1, 0.0f);
                v2 = fmaxf((v2 - m0) * s0 + t0, 0.0f);
                v3 = fmaxf((v3 - m1) * s1 + t1, 0.0f);
            }
            if (m_a < N_NODES)
                *(float2*)(C + (size_t)m_a * NTOT + n) = make_float2(v0, v1);
            if (m_b < N_NODES)
                *(float2*)(C + (size_t)m_b * NTOT + n) = make_float2(v2, v3);
        }
    }
}

// ---------------- pooling: mean + max per graph ----------------------------
__global__ void k_pool(const float* __restrict__ h3, float* __restrict__ out) {
    int g = blockIdx.x;
    int tx = threadIdx.x;
    int s = g_gstart[g], e = g_gstart[g + 1];
    float sum[3] = {0.f, 0.f, 0.f};
    float mx[3]  = {-INFINITY, -INFINITY, -INFINITY};
    for (int n = s; n < e; n++) {
#pragma unroll
        for (int c = 0; c < 3; c++) {
            float v = h3[(size_t)n * 384 + tx + c * 128];
            sum[c] += v;
            mx[c] = fmaxf(mx[c], v);
        }
    }
    float inv = 1.0f / fmaxf((float)(e - s), 1.0f);
#pragma unroll
    for (int c = 0; c < 3; c++)
        out[(size_t)g * 384 + tx + c * 128] = sum[c] * inv + mx[c];
}

// ---------------- launch ----------------------------------------------------
extern "C" void kernel_launch(void* const* d_in, const int* in_sizes, int n_in,
                              void* d_out, int out_size) {
    const float* x     = (const float*)d_in[0];
    const int*   ei    = (const int*)d_in[1];   // [2, E] int32
    const int*   src   = ei;
    const int*   dst   = ei + N_EDGES;
    const int*   batch = (const int*)d_in[2];
    const float* W1 = (const float*)d_in[3];
    const float* b1 = (const float*)d_in[4];
    const float* g1 = (const float*)d_in[5];
    const float* be1 = (const float*)d_in[6];
    const float* rm1 = (const float*)d_in[7];
    const float* rv1 = (const float*)d_in[8];
    const float* W2 = (const float*)d_in[9];
    const float* b2 = (const float*)d_in[10];
    const float* g2 = (const float*)d_in[11];
    const float* be2 = (const float*)d_in[12];
    const float* rm2 = (const float*)d_in[13];
    const float* rv2 = (const float*)d_in[14];
    const float* W3 = (const float*)d_in[15];
    const float* b3 = (const float*)d_in[16];
    float* out = (float*)d_out;

    float *p_buf1, *p_buf2;
    __half *p_Aaug, *p_Baug;
    int *p_deg, *p_rowstart, *p_cursor, *p_gcnt, *p_bsums;
    cudaGetSymbolAddress((void**)&p_buf1, g_buf1);
    cudaGetSymbolAddress((void**)&p_buf2, g_buf2);
    cudaGetSymbolAddress((void**)&p_Aaug, g_Aaug);
    cudaGetSymbolAddress((void**)&p_Baug, g_Baug);
    cudaGetSymbolAddress((void**)&p_deg, g_deg);
    cudaGetSymbolAddress((void**)&p_rowstart, g_rowstart);
    cudaGetSymbolAddress((void**)&p_cursor, g_cursor);
    cudaGetSymbolAddress((void**)&p_gcnt, g_gcnt);
    cudaGetSymbolAddress((void**)&p_bsums, g_bsums);

    // zeroing via memset nodes (do not shift the ncu kernel-launch index)
    cudaMemsetAsync(p_deg, 0, N_NODES * sizeof(int));
    cudaMemsetAsync(p_gcnt, 0, N_GRAPHS * sizeof(int));

    // ---- CSR construction: launches 1..5 ----
    k_hist<<<(N_EDGES + 255) / 256, 256>>>(dst, batch);                        // 1
    k_scan_block<<<SCAN_BLOCKS, 1024>>>(p_deg, p_rowstart, N_NODES, p_bsums);  // 2
    k_scan_sums<<<1, 128>>>(p_bsums, SCAN_BLOCKS);                             // 3
    k_scan_add<<<SCAN_BLOCKS, 1024>>>(p_rowstart, N_NODES, p_bsums,
                                      N_EDGES, p_cursor);                      // 4
    k_fill<<<(N_EDGES + 255) / 256, 256>>>(src, dst);                          // 5

    const int AGG_BLOCKS = (N_NODES + 7) / 8;   // 8 warps/block

    // ---- Layer 1: agg(x)[100k,74] -> fp16 [hi|lo] K=160, GEMM+BN+ReLU ----
    k_agg_pre74<<<AGG_BLOCKS, 256>>>(x, p_Aaug);                               // 6 (profiled)
    {
        size_t nb = (size_t)256 * 80;
        k_convB<<<(int)((nb + 255) / 256), 256>>>(W1, p_Baug, 74, 256, 80);    // 7
        dim3 grid(256 / 128, MPAD / 128);
        k_gemm_mma<1><<<grid, 256>>>(p_Aaug, p_Baug, p_buf2, 160, 256,
                                     b1, g1, be1, rm1, rv1);                   // 8
    }
    // ---- Layer 2 ----
    {
        size_t nb = (size_t)256 * 256;
        k_convB<<<(int)((nb + 255) / 256), 256>>>(W2, p_Baug, 256, 256, 256);  // 9
        k_agg_pre256<<<AGG_BLOCKS, 256>>>(p_buf2, p_Aaug);                     // 10
        dim3 grid(256 / 128, MPAD / 128);
        k_gemm_mma<1><<<grid, 256>>>(p_Aaug, p_Baug, p_buf2, 512, 256,
                                     b2, g2, be2, rm2, rv2);                   // 11
    }
    // ---- Layer 3 ----
    {
        size_t nb = (size_t)384 * 256;
        k_convB<<<(int)((nb + 255) / 256), 256>>>(W3, p_Baug, 256, 384, 256);  // 12
        k_agg_pre256<<<AGG_BLOCKS, 256>>>(p_buf2, p_Aaug);                     // 13
        dim3 grid(384 / 128, MPAD / 128);
        k_gemm_mma<0><<<grid, 256>>>(p_Aaug, p_Baug, p_buf1, 512, 384,
                                     b3, (const float*)0, (const float*)0,
                                     (const float*)0, (const float*)0);        // 14
    }
    // ---- pooling segments + mean+max pool ----
    k_scan_graphs<<<1, 1024>>>();                                              // 15
    k_pool<<<N_GRAPHS, 128>>>(p_buf1, out);                                    // 16
}

// round 8
// speedup vs baseline: 3.3377x; 1.2369x over previous
#include <cuda_runtime.h>
#include <cuda_fp16.h>
#include <math.h>
#include <cstdint>

#define N_NODES  100000
#define N_EDGES  1600000
#define N_GRAPHS 2048
#define SCAN_BLOCKS ((N_NODES + 1023) / 1024)   // 98
#define MPAD 100096                              // 782 * 128

// ---------------- scratch (device globals: no allocation allowed) ----------
__device__ float  g_buf1[(size_t)N_NODES * 384];           // h3 (fp32)
__device__ __half g_bufh[(size_t)N_NODES * 256];           // h1, h2 (fp16)
__device__ __half g_Aaug[(size_t)MPAD * 512];              // [MPAD, 2*KS]
__device__ __half g_Baug[(size_t)384 * 512];               // [NTOT, 2*KS]
__device__ int   g_deg[N_NODES];
__device__ int   g_rowstart[N_NODES + 1];
__device__ int   g_cursor[N_NODES];
__device__ int   g_csr[N_EDGES];
__device__ float g_dinv[N_NODES];
__device__ int   g_gcnt[N_GRAPHS];
__device__ int   g_gstart[N_GRAPHS + 1];
__device__ int   g_bsums[128];

// ======================= low-level helpers ==================================
__device__ __forceinline__ uint32_t smem_u32(const void* p) {
    uint32_t a;
    asm("{ .reg .u64 t; cvta.to.shared.u64 t, %1; cvt.u32.u64 %0, t; }"
        : "=r"(a) : "l"(p));
    return a;
}

__device__ __forceinline__ void cp_async16(uint32_t dst, const void* src) {
    asm volatile("cp.async.cg.shared.global [%0], [%1], 16;"
                 :: "r"(dst), "l"(src));
}
__device__ __forceinline__ void cp_commit() {
    asm volatile("cp.async.commit_group;");
}
__device__ __forceinline__ void cp_wait1() {
    asm volatile("cp.async.wait_group 1;");
}
__device__ __forceinline__ void cp_wait0() {
    asm volatile("cp.async.wait_group 0;");
}

__device__ __forceinline__ void ldsm_x4(uint32_t& r0, uint32_t& r1,
                                        uint32_t& r2, uint32_t& r3, uint32_t addr) {
    asm volatile("ldmatrix.sync.aligned.m8n8.x4.shared.b16 {%0,%1,%2,%3}, [%4];"
                 : "=r"(r0), "=r"(r1), "=r"(r2), "=r"(r3) : "r"(addr));
}

__device__ __forceinline__ void mma16816(float* c, const uint32_t* a, const uint32_t* b) {
    asm volatile(
        "mma.sync.aligned.m16n8k16.row.col.f32.f16.f16.f32 "
        "{%0,%1,%2,%3}, {%4,%5,%6,%7}, {%8,%9}, {%0,%1,%2,%3};"
        : "+f"(c[0]), "+f"(c[1]), "+f"(c[2]), "+f"(c[3])
        : "r"(a[0]), "r"(a[1]), "r"(a[2]), "r"(a[3]), "r"(b[0]), "r"(b[1]));
}

__device__ __forceinline__ uint32_t pack_hf2(__half a, __half b) {
    __half2 t = __halves2half2(a, b);
    return *(uint32_t*)&t;
}

__device__ __forceinline__ float2 unpack_w(uint32_t w) {
    return __half22float2(*reinterpret_cast<const __half2*>(&w));
}

// ---------------- fused histogram: deg (edges) + gcnt (nodes) ---------------
__global__ void k_hist(const int* __restrict__ dst, const int* __restrict__ batch) {
    int i = blockIdx.x * blockDim.x + threadIdx.x;
    if (i < N_EDGES) atomicAdd(&g_deg[dst[i]], 1);
    if (i < N_NODES) atomicAdd(&g_gcnt[batch[i]], 1);
}

// ---------------- exclusive scan over deg (3 kernels, dinv fused) -----------
__global__ void k_scan_block(const int* __restrict__ in, int* __restrict__ out,
                             int n, int* __restrict__ bsums) {
    __shared__ int sm[1024];
    int i = blockIdx.x * 1024 + threadIdx.x;
    int v = (i < n) ? in[i] : 0;
    sm[threadIdx.x] = v;
    __syncthreads();
    for (int off = 1; off < 1024; off <<= 1) {
        int t = (threadIdx.x >= off) ? sm[threadIdx.x - off] : 0;
        __syncthreads();
        sm[threadIdx.x] += t;
        __syncthreads();
    }
    if (i < n) out[i] = sm[threadIdx.x] - v;           // exclusive
    if (threadIdx.x == 1023) bsums[blockIdx.x] = sm[1023];
}

__global__ void k_scan_sums(int* __restrict__ bsums, int nb) {  // 1 block, 128 thr
    __shared__ int sm[128];
    int v = (threadIdx.x < nb) ? bsums[threadIdx.x] : 0;
    sm[threadIdx.x] = v;
    __syncthreads();
    for (int off = 1; off < 128; off <<= 1) {
        int t = (threadIdx.x >= off) ? sm[threadIdx.x - off] : 0;
        __syncthreads();
        sm[threadIdx.x] += t;
        __syncthreads();
    }
    if (threadIdx.x < nb) bsums[threadIdx.x] = sm[threadIdx.x] - v;  // exclusive
}

// rowstart += block offset; also cursor copy + dinv (deg still in g_deg)
__global__ void k_scan_add(int* __restrict__ out, int n,
                           const int* __restrict__ bsums, int total,
                           int* __restrict__ cursor) {
    int i = blockIdx.x * 1024 + threadIdx.x;
    if (i < n) {
        int v = out[i] + bsums[blockIdx.x];
        out[i] = v;
        cursor[i] = v;
        g_dinv[i] = rsqrtf((float)g_deg[i] + 1.0f);
    }
    if (i == 0) out[n] = total;
}

__global__ void k_fill(const int* __restrict__ src, const int* __restrict__ dst) {
    int e = blockIdx.x * blockDim.x + threadIdx.x;
    if (e < N_EDGES) {
        int d = dst[e];
        int p = atomicAdd(&g_cursor[d], 1);
        g_csr[p] = src[e];
    }
}

// ---------------- single-block scan for graph segments (2048 bins) ----------
__global__ void k_scan_graphs() {
    __shared__ int sm[2048];
    int t = threadIdx.x;
    int v0 = g_gcnt[t], v1 = g_gcnt[t + 1024];
    sm[t] = v0; sm[t + 1024] = v1;
    __syncthreads();
    for (int off = 1; off < 2048; off <<= 1) {
        int i1 = t + 1024;
        int t0 = (t >= off) ? sm[t - off] : 0;
        int t1 = (i1 >= off) ? sm[i1 - off] : 0;
        __syncthreads();
        sm[t] += t0; sm[i1] += t1;
        __syncthreads();
    }
    g_gstart[t] = sm[t] - v0;
    g_gstart[t + 1024] = sm[t + 1024] - v1;
    if (t == 0) g_gstart[2048] = N_NODES;
}

// ---------------- B: W [K,N] fp32 -> Baug [N, 2*KS] fp16 (hi|hi) ------------
__global__ void k_convB(const float* __restrict__ W,
                        __half* __restrict__ Baug,
                        int Kreal, int N, int KS) {
    size_t idx = (size_t)blockIdx.x * blockDim.x + threadIdx.x;
    size_t total = (size_t)N * KS;
    if (idx >= total) return;
    int n = (int)(idx / KS);
    int k = (int)(idx % KS);
    float v = (k < Kreal) ? W[(size_t)k * N + n] : 0.0f;
    __half h = __float2half_rn(v);
    size_t base = (size_t)n * (2 * KS) + k;
    Baug[base]      = h;
    Baug[base + KS] = h;
}

// ---------------- layer-1 aggregate: x [N,74] -> Aaug [N, 160] (hi|lo) ------
__global__ void k_agg_pre74(const float* __restrict__ x,
                            __half* __restrict__ Aaug) {
    int gw = (int)((blockIdx.x * blockDim.x + threadIdx.x) >> 5);
    if (gw >= N_NODES) return;
    int lane = threadIdx.x & 31;
    int rs = g_rowstart[gw], re = g_rowstart[gw + 1];
    float di = g_dinv[gw];
    float self = di * di;
    const float* row = x + (size_t)gw * 74;
    float a0 = row[lane] * self;
    float a1 = row[lane + 32] * self;
    float a2 = (lane < 10) ? row[lane + 64] * self : 0.0f;
    for (int e0 = rs; e0 < re; e0 += 32) {
        int cnt = min(32, re - e0);
        int sreg = 0; float dreg = 0.0f;
        if (e0 + lane < re) {
            sreg = g_csr[e0 + lane];
            dreg = g_dinv[sreg];
        }
        for (int j = 0; j < cnt; j++) {
            int s = __shfl_sync(0xffffffffu, sreg, j);
            float nrm = __shfl_sync(0xffffffffu, dreg, j) * di;
            const float* sr = x + (size_t)s * 74;
            a0 += sr[lane] * nrm;
            a1 += sr[lane + 32] * nrm;
            if (lane < 10) a2 += sr[lane + 64] * nrm;
        }
    }
    // emit hi at col, lo at col+80 (row width 160), cols 74..79 zero
    size_t base = (size_t)gw * 160;
    {
        __half h = __float2half_rn(a0);
        __half l = __float2half_rn(a0 - __half2float(h));
        Aaug[base + lane] = h; Aaug[base + 80 + lane] = l;
    }
    {
        __half h = __float2half_rn(a1);
        __half l = __float2half_rn(a1 - __half2float(h));
        Aaug[base + lane + 32] = h; Aaug[base + 80 + lane + 32] = l;
    }
    if (lane < 16) {   // cols 64..79; lanes 10..15 emit zeros (a2 stays 0)
        __half h = __float2half_rn(a2);
        __half l = __float2half_rn(a2 - __half2float(h));
        Aaug[base + lane + 64] = h; Aaug[base + 80 + lane + 64] = l;
    }
}

// ---------------- aggregate (F=256, fp16 in): one warp per node --------------
// Each lane owns 8 consecutive columns = ONE uint4 (8 halves) load per edge.
// 32 lanes x 8 = 256 columns exactly. hi -> cols [0,256), lo -> cols [256,512).
__global__ void k_agg_pre256h(const __half* __restrict__ hin,
                              __half* __restrict__ Aaug) {
    int gw = (int)((blockIdx.x * blockDim.x + threadIdx.x) >> 5);
    if (gw >= N_NODES) return;
    int lane = threadIdx.x & 31;
    int rs = g_rowstart[gw], re = g_rowstart[gw + 1];
    float di = g_dinv[gw];
    float self = di * di;
    float acc[8];
    {
        uint4 t = *(const uint4*)(hin + (size_t)gw * 256 + lane * 8);
        float2 f0 = unpack_w(t.x), f1 = unpack_w(t.y);
        float2 f2 = unpack_w(t.z), f3 = unpack_w(t.w);
        acc[0] = f0.x * self; acc[1] = f0.y * self;
        acc[2] = f1.x * self; acc[3] = f1.y * self;
        acc[4] = f2.x * self; acc[5] = f2.y * self;
        acc[6] = f3.x * self; acc[7] = f3.y * self;
    }
    for (int e0 = rs; e0 < re; e0 += 32) {
        int cnt = min(32, re - e0);
        int sreg = 0; float dreg = 0.0f;
        if (e0 + lane < re) {
            sreg = g_csr[e0 + lane];
            dreg = g_dinv[sreg];
        }
        for (int j = 0; j < cnt; j++) {
            int s = __shfl_sync(0xffffffffu, sreg, j);
            float nrm = __shfl_sync(0xffffffffu, dreg, j) * di;
            uint4 t = *(const uint4*)(hin + (size_t)s * 256 + lane * 8);
            float2 f0 = unpack_w(t.x), f1 = unpack_w(t.y);
            float2 f2 = unpack_w(t.z), f3 = unpack_w(t.w);
            acc[0] += f0.x * nrm; acc[1] += f0.y * nrm;
            acc[2] += f1.x * nrm; acc[3] += f1.y * nrm;
            acc[4] += f2.x * nrm; acc[5] += f2.y * nrm;
            acc[6] += f3.x * nrm; acc[7] += f3.y * nrm;
        }
    }
    // ---- emit hi/lo via register packing ----
    uint32_t hpk[4], lpk[4];
#pragma unroll
    for (int q = 0; q < 4; q++) {
        __half h0 = __float2half_rn(acc[2 * q]);
        __half h1 = __float2half_rn(acc[2 * q + 1]);
        __half l0 = __float2half_rn(acc[2 * q]     - __half2float(h0));
        __half l1 = __float2half_rn(acc[2 * q + 1] - __half2float(h1));
        hpk[q] = pack_hf2(h0, h1);
        lpk[q] = pack_hf2(l0, l1);
    }
    size_t obase = (size_t)gw * 512 + lane * 8;   // halves; byte addr 16B-aligned
    *(uint4*)(Aaug + obase)       = make_uint4(hpk[0], hpk[1], hpk[2], hpk[3]);
    *(uint4*)(Aaug + obase + 256) = make_uint4(lpk[0], lpk[1], lpk[2], lpk[3]);
}

// ---------------- fp16 mma.sync GEMM + fused epilogue ------------------------
// C[m,n] = sum_k Aaug[m,k] * Baug[n,k]
// EPI: 0 = +bias -> fp32 out ; 1 = +bias,BN,ReLU -> fp16 out
#define GS 40   // smem row stride in halves (32 data + 8 pad = 80B, conflict-free)

template <int EPI>
__global__ __launch_bounds__(256, 2)
void k_gemm_mma(const __half* __restrict__ A,
                const __half* __restrict__ B,
                float* __restrict__ C, __half* __restrict__ Ch,
                int K, int NTOT,
                const float* __restrict__ bias,
                const float* __restrict__ gamma,
                const float* __restrict__ beta,
                const float* __restrict__ rm,
                const float* __restrict__ rv) {
    __shared__ __align__(16) __half As[2][128 * GS];
    __shared__ __align__(16) __half Bs[2][128 * GS];

    int tid = threadIdx.x;
    int wid = tid >> 5, lane = tid & 31;
    int warp_m = wid & 1;
    int warp_n = wid >> 1;
    int rowBase = blockIdx.y * 128;
    int colBase = blockIdx.x * 128;

    uint32_t asb = smem_u32(&As[0][0]);
    uint32_t bsb = smem_u32(&Bs[0][0]);
    const uint32_t bufBytes = 128 * GS * 2;

    float acc[4][4][4];
#pragma unroll
    for (int i = 0; i < 4; i++)
#pragma unroll
        for (int j = 0; j < 4; j++)
#pragma unroll
            for (int q = 0; q < 4; q++) acc[i][j][q] = 0.0f;

    const int NC = K >> 5;

    auto load_chunk = [&](int c, int buf) {
        int k0 = c << 5;
#pragma unroll
        for (int t = 0; t < 2; t++) {
            int idx = tid + (t << 8);
            int r = idx >> 2, seg = idx & 3;
            uint32_t doff = (uint32_t)(r * GS + seg * 8) * 2;
            cp_async16(asb + buf * bufBytes + doff,
                       A + (size_t)(rowBase + r) * K + k0 + seg * 8);
            cp_async16(bsb + buf * bufBytes + doff,
                       B + (size_t)(colBase + r) * K + k0 + seg * 8);
        }
        cp_commit();
    };

    load_chunk(0, 0);

    for (int c = 0; c < NC; c++) {
        int buf = c & 1;
        if (c + 1 < NC) {
            load_chunk(c + 1, buf ^ 1);
            cp_wait1();
        } else {
            cp_wait0();
        }
        __syncthreads();

        uint32_t aBase = asb + buf * bufBytes;
        uint32_t bBase = bsb + buf * bufBytes;
#pragma unroll
        for (int kk = 0; kk < 2; kk++) {
            uint32_t af[4][4];
            {
                int row = warp_m * 64 + (lane & 15);
                int kcol = kk * 16 + ((lane >> 4) << 3);
#pragma unroll
                for (int i = 0; i < 4; i++) {
                    uint32_t addr = aBase + (uint32_t)((row + i * 16) * GS + kcol) * 2;
                    ldsm_x4(af[i][0], af[i][1], af[i][2], af[i][3], addr);
                }
            }
            uint32_t bf[4][2];
            {
                int rown = warp_n * 32 + (lane & 7) + ((lane & 16) ? 8 : 0);
                int kcol = kk * 16 + ((lane & 8) ? 8 : 0);
#pragma unroll
                for (int jj = 0; jj < 2; jj++) {
                    uint32_t addr = bBase + (uint32_t)((rown + jj * 16) * GS + kcol) * 2;
                    ldsm_x4(bf[jj * 2][0], bf[jj * 2][1],
                            bf[jj * 2 + 1][0], bf[jj * 2 + 1][1], addr);
                }
            }
#pragma unroll
            for (int i = 0; i < 4; i++)
#pragma unroll
                for (int j = 0; j < 4; j++)
                    mma16816(acc[i][j], af[i], bf[j]);
        }
        __syncthreads();
    }

    int mrow0 = rowBase + warp_m * 64 + (lane >> 2);
    int ncol0 = colBase + warp_n * 32 + ((lane & 3) << 1);
#pragma unroll
    for (int j = 0; j < 4; j++) {
        int n = ncol0 + j * 8;
        float b0 = bias[n], b1 = bias[n + 1];
        float s0 = 0.f, s1 = 0.f, t0 = 0.f, t1 = 0.f, m0 = 0.f, m1 = 0.f;
        if (EPI) {
            s0 = gamma[n]     * rsqrtf(rv[n]     + 1e-5f);
            s1 = gamma[n + 1] * rsqrtf(rv[n + 1] + 1e-5f);
            t0 = beta[n];  t1 = beta[n + 1];
            m0 = rm[n];    m1 = rm[n + 1];
        }
#pragma unroll
        for (int i = 0; i < 4; i++) {
            int m_a = mrow0 + i * 16;
            int m_b = m_a + 8;
            float v0 = acc[i][j][0] + b0, v1 = acc[i][j][1] + b1;
            float v2 = acc[i][j][2] + b0, v3 = acc[i][j][3] + b1;
            if (EPI) {
                v0 = fmaxf((v0 - m0) * s0 + t0, 0.0f);
                v1 = fmaxf((v1 - m1) * s1 + t1, 0.0f);
                v2 = fmaxf((v2 - m0) * s0 + t0, 0.0f);
                v3 = fmaxf((v3 - m1) * s1 + t1, 0.0f);
                if (m_a < N_NODES) {
                    uint32_t p = pack_hf2(__float2half_rn(v0), __float2half_rn(v1));
                    *(uint32_t*)(Ch + (size_t)m_a * NTOT + n) = p;
                }
                if (m_b < N_NODES) {
                    uint32_t p = pack_hf2(__float2half_rn(v2), __float2half_rn(v3));
                    *(uint32_t*)(Ch + (size_t)m_b * NTOT + n) = p;
                }
            } else {
                if (m_a < N_NODES)
                    *(float2*)(C + (size_t)m_a * NTOT + n) = make_float2(v0, v1);
                if (m_b < N_NODES)
                    *(float2*)(C + (size_t)m_b * NTOT + n) = make_float2(v2, v3);
            }
        }
    }
}

// ---------------- pooling: mean + max per graph ----------------------------
__global__ void k_pool(const float* __restrict__ h3, float* __restrict__ out) {
    int g = blockIdx.x;
    int tx = threadIdx.x;
    int s = g_gstart[g], e = g_gstart[g + 1];
    float sum[3] = {0.f, 0.f, 0.f};
    float mx[3]  = {-INFINITY, -INFINITY, -INFINITY};
    for (int n = s; n < e; n++) {
#pragma unroll
        for (int c = 0; c < 3; c++) {
            float v = h3[(size_t)n * 384 + tx + c * 128];
            sum[c] += v;
            mx[c] = fmaxf(mx[c], v);
        }
    }
    float inv = 1.0f / fmaxf((float)(e - s), 1.0f);
#pragma unroll
    for (int c = 0; c < 3; c++)
        out[(size_t)g * 384 + tx + c * 128] = sum[c] * inv + mx[c];
}

// ---------------- launch ----------------------------------------------------
extern "C" void kernel_launch(void* const* d_in, const int* in_sizes, int n_in,
                              void* d_out, int out_size) {
    const float* x     = (const float*)d_in[0];
    const int*   ei    = (const int*)d_in[1];   // [2, E] int32
    const int*   src   = ei;
    const int*   dst   = ei + N_EDGES;
    const int*   batch = (const int*)d_in[2];
    const float* W1 = (const float*)d_in[3];
    const float* b1 = (const float*)d_in[4];
    const float* g1 = (const float*)d_in[5];
    const float* be1 = (const float*)d_in[6];
    const float* rm1 = (const float*)d_in[7];
    const float* rv1 = (const float*)d_in[8];
    const float* W2 = (const float*)d_in[9];
    const float* b2 = (const float*)d_in[10];
    const float* g2 = (const float*)d_in[11];
    const float* be2 = (const float*)d_in[12];
    const float* rm2 = (const float*)d_in[13];
    const float* rv2 = (const float*)d_in[14];
    const float* W3 = (const float*)d_in[15];
    const float* b3 = (const float*)d_in[16];
    float* out = (float*)d_out;

    float *p_buf1;
    __half *p_bufh, *p_Aaug, *p_Baug;
    int *p_deg, *p_rowstart, *p_cursor, *p_gcnt, *p_bsums;
    cudaGetSymbolAddress((void**)&p_buf1, g_buf1);
    cudaGetSymbolAddress((void**)&p_bufh, g_bufh);
    cudaGetSymbolAddress((void**)&p_Aaug, g_Aaug);
    cudaGetSymbolAddress((void**)&p_Baug, g_Baug);
    cudaGetSymbolAddress((void**)&p_deg, g_deg);
    cudaGetSymbolAddress((void**)&p_rowstart, g_rowstart);
    cudaGetSymbolAddress((void**)&p_cursor, g_cursor);
    cudaGetSymbolAddress((void**)&p_gcnt, g_gcnt);
    cudaGetSymbolAddress((void**)&p_bsums, g_bsums);

    // zeroing via memset nodes
    cudaMemsetAsync(p_deg, 0, N_NODES * sizeof(int));
    cudaMemsetAsync(p_gcnt, 0, N_GRAPHS * sizeof(int));

    // ---- CSR construction ----
    k_hist<<<(N_EDGES + 255) / 256, 256>>>(dst, batch);
    k_scan_block<<<SCAN_BLOCKS, 1024>>>(p_deg, p_rowstart, N_NODES, p_bsums);
    k_scan_sums<<<1, 128>>>(p_bsums, SCAN_BLOCKS);
    k_scan_add<<<SCAN_BLOCKS, 1024>>>(p_rowstart, N_NODES, p_bsums,
                                      N_EDGES, p_cursor);
    k_fill<<<(N_EDGES + 255) / 256, 256>>>(src, dst);

    const int AGG_BLOCKS = (N_NODES + 7) / 8;   // 8 warps/block

    // ---- Layer 1: agg(x)[100k,74] -> fp16 [hi|lo] K=160, GEMM+BN+ReLU -> fp16 h1
    k_agg_pre74<<<AGG_BLOCKS, 256>>>(x, p_Aaug);
    {
        size_t nb = (size_t)256 * 80;
        k_convB<<<(int)((nb + 255) / 256), 256>>>(W1, p_Baug, 74, 256, 80);
        dim3 grid(256 / 128, MPAD / 128);
        k_gemm_mma<1><<<grid, 256>>>(p_Aaug, p_Baug, (float*)0, p_bufh, 160, 256,
                                     b1, g1, be1, rm1, rv1);
    }
    // ---- Layer 2: agg(h1 fp16) -> GEMM+BN+ReLU -> fp16 h2 ----
    {
        size_t nb = (size_t)256 * 256;
        k_convB<<<(int)((nb + 255) / 256), 256>>>(W2, p_Baug, 256, 256, 256);
        k_agg_pre256h<<<AGG_BLOCKS, 256>>>(p_bufh, p_Aaug);
        dim3 grid(256 / 128, MPAD / 128);
        k_gemm_mma<1><<<grid, 256>>>(p_Aaug, p_Baug, (float*)0, p_bufh, 512, 256,
                                     b2, g2, be2, rm2, rv2);
    }
    // ---- Layer 3: agg(h2 fp16) -> GEMM +b3 -> fp32 h3 ----
    {
        size_t nb = (size_t)384 * 256;
        k_convB<<<(int)((nb + 255) / 256), 256>>>(W3, p_Baug, 256, 384, 256);
        k_agg_pre256h<<<AGG_BLOCKS, 256>>>(p_bufh, p_Aaug);
        dim3 grid(384 / 128, MPAD / 128);
        k_gemm_mma<0><<<grid, 256>>>(p_Aaug, p_Baug, p_buf1, (__half*)0, 512, 384,
                                     b3, (const float*)0, (const float*)0,
                                     (const float*)0, (const float*)0);
    }
    // ---- pooling segments + mean+max pool ----
    k_scan_graphs<<<1, 1024>>>();
    k_pool<<<N_GRAPHS, 128>>>(p_buf1, out);
}

// round 9
// speedup vs baseline: 4.2579x; 1.2757x over previous
#include <cuda_runtime.h>
#include <cuda_fp16.h>
#include <math.h>
#include <cstdint>

#define N_NODES  100000
#define N_EDGES  1600000
#define N_GRAPHS 2048
#define SCAN_BLOCKS ((N_NODES + 1023) / 1024)   // 98
#define MPAD 100096                              // 782 * 128

// ---------------- scratch (device globals: no allocation allowed) ----------
__device__ float  g_buf1[(size_t)N_NODES * 384];           // h3 (fp32)
__device__ __half g_bufh[(size_t)N_NODES * 256];           // h1, h2 (fp16)
__device__ __half g_Aaug[(size_t)MPAD * 256];              // [MPAD, KS] fp16
__device__ __half g_Baug[(size_t)384 * 256];               // [NTOT, KS] fp16
__device__ int   g_deg[N_NODES];
__device__ int   g_rowstart[N_NODES + 1];
__device__ int   g_cursor[N_NODES];
__device__ int   g_csr[N_EDGES];
__device__ float g_dinv[N_NODES];
__device__ int   g_gcnt[N_GRAPHS];
__device__ int   g_gstart[N_GRAPHS + 1];
__device__ int   g_bsums[128];

// ======================= low-level helpers ==================================
__device__ __forceinline__ uint32_t smem_u32(const void* p) {
    uint32_t a;
    asm("{ .reg .u64 t; cvta.to.shared.u64 t, %1; cvt.u32.u64 %0, t; }"
        : "=r"(a) : "l"(p));
    return a;
}

__device__ __forceinline__ void cp_async16(uint32_t dst, const void* src) {
    asm volatile("cp.async.cg.shared.global [%0], [%1], 16;"
                 :: "r"(dst), "l"(src));
}
__device__ __forceinline__ void cp_commit() {
    asm volatile("cp.async.commit_group;");
}
__device__ __forceinline__ void cp_wait1() {
    asm volatile("cp.async.wait_group 1;");
}
__device__ __forceinline__ void cp_wait0() {
    asm volatile("cp.async.wait_group 0;");
}

__device__ __forceinline__ void ldsm_x4(uint32_t& r0, uint32_t& r1,
                                        uint32_t& r2, uint32_t& r3, uint32_t addr) {
    asm volatile("ldmatrix.sync.aligned.m8n8.x4.shared.b16 {%0,%1,%2,%3}, [%4];"
                 : "=r"(r0), "=r"(r1), "=r"(r2), "=r"(r3) : "r"(addr));
}

__device__ __forceinline__ void mma16816(float* c, const uint32_t* a, const uint32_t* b) {
    asm volatile(
        "mma.sync.aligned.m16n8k16.row.col.f32.f16.f16.f32 "
        "{%0,%1,%2,%3}, {%4,%5,%6,%7}, {%8,%9}, {%0,%1,%2,%3};"
        : "+f"(c[0]), "+f"(c[1]), "+f"(c[2]), "+f"(c[3])
        : "r"(a[0]), "r"(a[1]), "r"(a[2]), "r"(a[3]), "r"(b[0]), "r"(b[1]));
}

__device__ __forceinline__ uint32_t pack_hf2(__half a, __half b) {
    __half2 t = __halves2half2(a, b);
    return *(uint32_t*)&t;
}

__device__ __forceinline__ float2 unpack_w(uint32_t w) {
    return __half22float2(*reinterpret_cast<const __half2*>(&w));
}

// ---------------- fused histogram: deg (edges) + gcnt (nodes) ---------------
__global__ void k_hist(const int* __restrict__ dst, const int* __restrict__ batch) {
    int i = blockIdx.x * blockDim.x + threadIdx.x;
    if (i < N_EDGES) atomicAdd(&g_deg[dst[i]], 1);
    if (i < N_NODES) atomicAdd(&g_gcnt[batch[i]], 1);
}

// ---------------- exclusive scan over deg (3 kernels, dinv fused) -----------
__global__ void k_scan_block(const int* __restrict__ in, int* __restrict__ out,
                             int n, int* __restrict__ bsums) {
    __shared__ int sm[1024];
    int i = blockIdx.x * 1024 + threadIdx.x;
    int v = (i < n) ? in[i] : 0;
    sm[threadIdx.x] = v;
    __syncthreads();
    for (int off = 1; off < 1024; off <<= 1) {
        int t = (threadIdx.x >= off) ? sm[threadIdx.x - off] : 0;
        __syncthreads();
        sm[threadIdx.x] += t;
        __syncthreads();
    }
    if (i < n) out[i] = sm[threadIdx.x] - v;           // exclusive
    if (threadIdx.x == 1023) bsums[blockIdx.x] = sm[1023];
}

__global__ void k_scan_sums(int* __restrict__ bsums, int nb) {  // 1 block, 128 thr
    __shared__ int sm[128];
    int v = (threadIdx.x < nb) ? bsums[threadIdx.x] : 0;
    sm[threadIdx.x] = v;
    __syncthreads();
    for (int off = 1; off < 128; off <<= 1) {
        int t = (threadIdx.x >= off) ? sm[threadIdx.x - off] : 0;
        __syncthreads();
        sm[threadIdx.x] += t;
        __syncthreads();
    }
    if (threadIdx.x < nb) bsums[threadIdx.x] = sm[threadIdx.x] - v;  // exclusive
}

// rowstart += block offset; also cursor copy + dinv (deg still in g_deg)
__global__ void k_scan_add(int* __restrict__ out, int n,
                           const int* __restrict__ bsums, int total,
                           int* __restrict__ cursor) {
    int i = blockIdx.x * 1024 + threadIdx.x;
    if (i < n) {
        int v = out[i] + bsums[blockIdx.x];
        out[i] = v;
        cursor[i] = v;
        g_dinv[i] = rsqrtf((float)g_deg[i] + 1.0f);
    }
    if (i == 0) out[n] = total;
}

__global__ void k_fill(const int* __restrict__ src, const int* __restrict__ dst) {
    int e = blockIdx.x * blockDim.x + threadIdx.x;
    if (e < N_EDGES) {
        int d = dst[e];
        int p = atomicAdd(&g_cursor[d], 1);
        g_csr[p] = src[e];
    }
}

// ---------------- single-block scan for graph segments (2048 bins) ----------
__global__ void k_scan_graphs() {
    __shared__ int sm[2048];
    int t = threadIdx.x;
    int v0 = g_gcnt[t], v1 = g_gcnt[t + 1024];
    sm[t] = v0; sm[t + 1024] = v1;
    __syncthreads();
    for (int off = 1; off < 2048; off <<= 1) {
        int i1 = t + 1024;
        int t0 = (t >= off) ? sm[t - off] : 0;
        int t1 = (i1 >= off) ? sm[i1 - off] : 0;
        __syncthreads();
        sm[t] += t0; sm[i1] += t1;
        __syncthreads();
    }
    g_gstart[t] = sm[t] - v0;
    g_gstart[t + 1024] = sm[t + 1024] - v1;
    if (t == 0) g_gstart[2048] = N_NODES;
}

// ---------------- B: W [K,N] fp32 -> Baug [N, KS] fp16 ----------------------
__global__ void k_convB(const float* __restrict__ W,
                        __half* __restrict__ Baug,
                        int Kreal, int N, int KS) {
    size_t idx = (size_t)blockIdx.x * blockDim.x + threadIdx.x;
    size_t total = (size_t)N * KS;
    if (idx >= total) return;
    int n = (int)(idx / KS);
    int k = (int)(idx % KS);
    float v = (k < Kreal) ? W[(size_t)k * N + n] : 0.0f;
    Baug[(size_t)n * KS + k] = __float2half_rn(v);
}

// ---------------- layer-1 aggregate: x [N,74] -> Aaug [N, 96] fp16 ----------
__global__ void k_agg_pre74(const float* __restrict__ x,
                            __half* __restrict__ Aaug) {
    int gw = (int)((blockIdx.x * blockDim.x + threadIdx.x) >> 5);
    if (gw >= N_NODES) return;
    int lane = threadIdx.x & 31;
    int rs = g_rowstart[gw], re = g_rowstart[gw + 1];
    float di = g_dinv[gw];
    float self = di * di;
    const float* row = x + (size_t)gw * 74;
    float a0 = row[lane] * self;
    float a1 = row[lane + 32] * self;
    float a2 = (lane < 10) ? row[lane + 64] * self : 0.0f;
    for (int e0 = rs; e0 < re; e0 += 32) {
        int cnt = min(32, re - e0);
        int sreg = 0; float dreg = 0.0f;
        if (e0 + lane < re) {
            sreg = g_csr[e0 + lane];
            dreg = g_dinv[sreg];
        }
        for (int j = 0; j < cnt; j++) {
            int s = __shfl_sync(0xffffffffu, sreg, j);
            float nrm = __shfl_sync(0xffffffffu, dreg, j) * di;
            const float* sr = x + (size_t)s * 74;
            a0 += sr[lane] * nrm;
            a1 += sr[lane + 32] * nrm;
            if (lane < 10) a2 += sr[lane + 64] * nrm;
        }
    }
    // emit fp16, row width 96; cols 74..95 are zeros (a2==0 for lanes >= 10)
    size_t base = (size_t)gw * 96;
    Aaug[base + lane]      = __float2half_rn(a0);
    Aaug[base + lane + 32] = __float2half_rn(a1);
    Aaug[base + lane + 64] = __float2half_rn(a2);
}

// ---------------- aggregate (F=256, fp16 in): one warp per node --------------
// Each lane owns 8 consecutive columns = ONE uint4 (8 halves) load per edge.
__global__ void k_agg_pre256h(const __half* __restrict__ hin,
                              __half* __restrict__ Aaug) {
    int gw = (int)((blockIdx.x * blockDim.x + threadIdx.x) >> 5);
    if (gw >= N_NODES) return;
    int lane = threadIdx.x & 31;
    int rs = g_rowstart[gw], re = g_rowstart[gw + 1];
    float di = g_dinv[gw];
    float self = di * di;
    float acc[8];
    {
        uint4 t = *(const uint4*)(hin + (size_t)gw * 256 + lane * 8);
        float2 f0 = unpack_w(t.x), f1 = unpack_w(t.y);
        float2 f2 = unpack_w(t.z), f3 = unpack_w(t.w);
        acc[0] = f0.x * self; acc[1] = f0.y * self;
        acc[2] = f1.x * self; acc[3] = f1.y * self;
        acc[4] = f2.x * self; acc[5] = f2.y * self;
        acc[6] = f3.x * self; acc[7] = f3.y * self;
    }
    for (int e0 = rs; e0 < re; e0 += 32) {
        int cnt = min(32, re - e0);
        int sreg = 0; float dreg = 0.0f;
        if (e0 + lane < re) {
            sreg = g_csr[e0 + lane];
            dreg = g_dinv[sreg];
        }
        for (int j = 0; j < cnt; j++) {
            int s = __shfl_sync(0xffffffffu, sreg, j);
            float nrm = __shfl_sync(0xffffffffu, dreg, j) * di;
            uint4 t = *(const uint4*)(hin + (size_t)s * 256 + lane * 8);
            float2 f0 = unpack_w(t.x), f1 = unpack_w(t.y);
            float2 f2 = unpack_w(t.z), f3 = unpack_w(t.w);
            acc[0] += f0.x * nrm; acc[1] += f0.y * nrm;
            acc[2] += f1.x * nrm; acc[3] += f1.y * nrm;
            acc[4] += f2.x * nrm; acc[5] += f2.y * nrm;
            acc[6] += f3.x * nrm; acc[7] += f3.y * nrm;
        }
    }
    uint32_t hpk[4];
#pragma unroll
    for (int q = 0; q < 4; q++)
        hpk[q] = pack_hf2(__float2half_rn(acc[2 * q]), __float2half_rn(acc[2 * q + 1]));
    size_t obase = (size_t)gw * 256 + lane * 8;   // 16B-aligned
    *(uint4*)(Aaug + obase) = make_uint4(hpk[0], hpk[1], hpk[2], hpk[3]);
}

// ---------------- fp16 mma.sync GEMM + fused epilogue ------------------------
// C[m,n] = sum_k Aaug[m,k] * Baug[n,k]
// EPI: 0 = +bias -> fp32 out ; 1 = +bias,BN,ReLU -> fp16 out
#define GS 40   // smem row stride in halves (32 data + 8 pad = 80B, conflict-free)

template <int EPI>
__global__ __launch_bounds__(256, 2)
void k_gemm_mma(const __half* __restrict__ A,
                const __half* __restrict__ B,
                float* __restrict__ C, __half* __restrict__ Ch,
                int K, int NTOT,
                const float* __restrict__ bias,
                const float* __restrict__ gamma,
                const float* __restrict__ beta,
                const float* __restrict__ rm,
                const float* __restrict__ rv) {
    __shared__ __align__(16) __half As[2][128 * GS];
    __shared__ __align__(16) __half Bs[2][128 * GS];

    int tid = threadIdx.x;
    int wid = tid >> 5, lane = tid & 31;
    int warp_m = wid & 1;
    int warp_n = wid >> 1;
    int rowBase = blockIdx.y * 128;
    int colBase = blockIdx.x * 128;

    uint32_t asb = smem_u32(&As[0][0]);
    uint32_t bsb = smem_u32(&Bs[0][0]);
    const uint32_t bufBytes = 128 * GS * 2;

    float acc[4][4][4];
#pragma unroll
    for (int i = 0; i < 4; i++)
#pragma unroll
        for (int j = 0; j < 4; j++)
#pragma unroll
            for (int q = 0; q < 4; q++) acc[i][j][q] = 0.0f;

    const int NC = K >> 5;

    auto load_chunk = [&](int c, int buf) {
        int k0 = c << 5;
#pragma unroll
        for (int t = 0; t < 2; t++) {
            int idx = tid + (t << 8);
            int r = idx >> 2, seg = idx & 3;
            uint32_t doff = (uint32_t)(r * GS + seg * 8) * 2;
            cp_async16(asb + buf * bufBytes + doff,
                       A + (size_t)(rowBase + r) * K + k0 + seg * 8);
            cp_async16(bsb + buf * bufBytes + doff,
                       B + (size_t)(colBase + r) * K + k0 + seg * 8);
        }
        cp_commit();
    };

    load_chunk(0, 0);

    for (int c = 0; c < NC; c++) {
        int buf = c & 1;
        if (c + 1 < NC) {
            load_chunk(c + 1, buf ^ 1);
            cp_wait1();
        } else {
            cp_wait0();
        }
        __syncthreads();

        uint32_t aBase = asb + buf * bufBytes;
        uint32_t bBase = bsb + buf * bufBytes;
#pragma unroll
        for (int kk = 0; kk < 2; kk++) {
            uint32_t af[4][4];
            {
                int row = warp_m * 64 + (lane & 15);
                int kcol = kk * 16 + ((lane >> 4) << 3);
#pragma unroll
                for (int i = 0; i < 4; i++) {
                    uint32_t addr = aBase + (uint32_t)((row + i * 16) * GS + kcol) * 2;
                    ldsm_x4(af[i][0], af[i][1], af[i][2], af[i][3], addr);
                }
            }
            uint32_t bf[4][2];
            {
                int rown = warp_n * 32 + (lane & 7) + ((lane & 16) ? 8 : 0);
                int kcol = kk * 16 + ((lane & 8) ? 8 : 0);
#pragma unroll
                for (int jj = 0; jj < 2; jj++) {
                    uint32_t addr = bBase + (uint32_t)((rown + jj * 16) * GS + kcol) * 2;
                    ldsm_x4(bf[jj * 2][0], bf[jj * 2][1],
                            bf[jj * 2 + 1][0], bf[jj * 2 + 1][1], addr);
                }
            }
#pragma unroll
            for (int i = 0; i < 4; i++)
#pragma unroll
                for (int j = 0; j < 4; j++)
                    mma16816(acc[i][j], af[i], bf[j]);
        }
        __syncthreads();
    }

    int mrow0 = rowBase + warp_m * 64 + (lane >> 2);
    int ncol0 = colBase + warp_n * 32 + ((lane & 3) << 1);
#pragma unroll
    for (int j = 0; j < 4; j++) {
        int n = ncol0 + j * 8;
        float b0 = bias[n], b1 = bias[n + 1];
        float s0 = 0.f, s1 = 0.f, t0 = 0.f, t1 = 0.f, m0 = 0.f, m1 = 0.f;
        if (EPI) {
            s0 = gamma[n]     * rsqrtf(rv[n]     + 1e-5f);
            s1 = gamma[n + 1] * rsqrtf(rv[n + 1] + 1e-5f);
            t0 = beta[n];  t1 = beta[n + 1];
            m0 = rm[n];    m1 = rm[n + 1];
        }
#pragma unroll
        for (int i = 0; i < 4; i++) {
            int m_a = mrow0 + i * 16;
            int m_b = m_a + 8;
            float v0 = acc[i][j][0] + b0, v1 = acc[i][j][1] + b1;
            float v2 = acc[i][j][2] + b0, v3 = acc[i][j][3] + b1;
            if (EPI) {
                v0 = fmaxf((v0 - m0) * s0 + t0, 0.0f);
                v1 = fmaxf((v1 - m1) * s1 + t1, 0.0f);
                v2 = fmaxf((v2 - m0) * s0 + t0, 0.0f);
                v3 = fmaxf((v3 - m1) * s1 + t1, 0.0f);
                if (m_a < N_NODES) {
                    uint32_t p = pack_hf2(__float2half_rn(v0), __float2half_rn(v1));
                    *(uint32_t*)(Ch + (size_t)m_a * NTOT + n) = p;
                }
                if (m_b < N_NODES) {
                    uint32_t p = pack_hf2(__float2half_rn(v2), __float2half_rn(v3));
                    *(uint32_t*)(Ch + (size_t)m_b * NTOT + n) = p;
                }
            } else {
                if (m_a < N_NODES)
                    *(float2*)(C + (size_t)m_a * NTOT + n) = make_float2(v0, v1);
                if (m_b < N_NODES)
                    *(float2*)(C + (size_t)m_b * NTOT + n) = make_float2(v2, v3);
            }
        }
    }
}

// ---------------- pooling: mean + max per graph ----------------------------
__global__ void k_pool(const float* __restrict__ h3, float* __restrict__ out) {
    int g = blockIdx.x;
    int tx = threadIdx.x;
    int s = g_gstart[g], e = g_gstart[g + 1];
    float sum[3] = {0.f, 0.f, 0.f};
    float mx[3]  = {-INFINITY, -INFINITY, -INFINITY};
    for (int n = s; n < e; n++) {
#pragma unroll
        for (int c = 0; c < 3; c++) {
            float v = h3[(size_t)n * 384 + tx + c * 128];
            sum[c] += v;
            mx[c] = fmaxf(mx[c], v);
        }
    }
    float inv = 1.0f / fmaxf((float)(e - s), 1.0f);
#pragma unroll
    for (int c = 0; c < 3; c++)
        out[(size_t)g * 384 + tx + c * 128] = sum[c] * inv + mx[c];
}

// ---------------- launch ----------------------------------------------------
extern "C" void kernel_launch(void* const* d_in, const int* in_sizes, int n_in,
                              void* d_out, int out_size) {
    const float* x     = (const float*)d_in[0];
    const int*   ei    = (const int*)d_in[1];   // [2, E] int32
    const int*   src   = ei;
    const int*   dst   = ei + N_EDGES;
    const int*   batch = (const int*)d_in[2];
    const float* W1 = (const float*)d_in[3];
    const float* b1 = (const float*)d_in[4];
    const float* g1 = (const float*)d_in[5];
    const float* be1 = (const float*)d_in[6];
    const float* rm1 = (const float*)d_in[7];
    const float* rv1 = (const float*)d_in[8];
    const float* W2 = (const float*)d_in[9];
    const float* b2 = (const float*)d_in[10];
    const float* g2 = (const float*)d_in[11];
    const float* be2 = (const float*)d_in[12];
    const float* rm2 = (const float*)d_in[13];
    const float* rv2 = (const float*)d_in[14];
    const float* W3 = (const float*)d_in[15];
    const float* b3 = (const float*)d_in[16];
    float* out = (float*)d_out;

    float *p_buf1;
    __half *p_bufh, *p_Aaug, *p_Baug;
    int *p_deg, *p_rowstart, *p_cursor, *p_gcnt, *p_bsums;
    cudaGetSymbolAddress((void**)&p_buf1, g_buf1);
    cudaGetSymbolAddress((void**)&p_bufh, g_bufh);
    cudaGetSymbolAddress((void**)&p_Aaug, g_Aaug);
    cudaGetSymbolAddress((void**)&p_Baug, g_Baug);
    cudaGetSymbolAddress((void**)&p_deg, g_deg);
    cudaGetSymbolAddress((void**)&p_rowstart, g_rowstart);
    cudaGetSymbolAddress((void**)&p_cursor, g_cursor);
    cudaGetSymbolAddress((void**)&p_gcnt, g_gcnt);
    cudaGetSymbolAddress((void**)&p_bsums, g_bsums);

    // zeroing via memset nodes
    cudaMemsetAsync(p_deg, 0, N_NODES * sizeof(int));
    cudaMemsetAsync(p_gcnt, 0, N_GRAPHS * sizeof(int));

    // ---- CSR construction ----
    k_hist<<<(N_EDGES + 255) / 256, 256>>>(dst, batch);
    k_scan_block<<<SCAN_BLOCKS, 1024>>>(p_deg, p_rowstart, N_NODES, p_bsums);
    k_scan_sums<<<1, 128>>>(p_bsums, SCAN_BLOCKS);
    k_scan_add<<<SCAN_BLOCKS, 1024>>>(p_rowstart, N_NODES, p_bsums,
                                      N_EDGES, p_cursor);
    k_fill<<<(N_EDGES + 255) / 256, 256>>>(src, dst);

    const int AGG_BLOCKS = (N_NODES + 7) / 8;   // 8 warps/block

    // ---- Layer 1: agg(x)[100k,74] -> fp16 K=96, GEMM+BN+ReLU -> fp16 h1 ----
    k_agg_pre74<<<AGG_BLOCKS, 256>>>(x, p_Aaug);
    {
        size_t nb = (size_t)256 * 96;
        k_convB<<<(int)((nb + 255) / 256), 256>>>(W1, p_Baug, 74, 256, 96);
        dim3 grid(256 / 128, MPAD / 128);
        k_gemm_mma<1><<<grid, 256>>>(p_Aaug, p_Baug, (float*)0, p_bufh, 96, 256,
                                     b1, g1, be1, rm1, rv1);
    }
    // ---- Layer 2: agg(h1 fp16) -> fp16 K=256, GEMM+BN+ReLU -> fp16 h2 ----
    {
        size_t nb = (size_t)256 * 256;
        k_convB<<<(int)((nb + 255) / 256), 256>>>(W2, p_Baug, 256, 256, 256);
        k_agg_pre256h<<<AGG_BLOCKS, 256>>>(p_bufh, p_Aaug);
        dim3 grid(256 / 128, MPAD / 128);
        k_gemm_mma<1><<<grid, 256>>>(p_Aaug, p_Baug, (float*)0, p_bufh, 256, 256,
                                     b2, g2, be2, rm2, rv2);
    }
    // ---- Layer 3: agg(h2 fp16) -> fp16 K=256, GEMM +b3 -> fp32 h3 ----
    {
        size_t nb = (size_t)384 * 256;
        k_convB<<<(int)((nb + 255) / 256), 256>>>(W3, p_Baug, 256, 384, 256);
        k_agg_pre256h<<<AGG_BLOCKS, 256>>>(p_bufh, p_Aaug);
        dim3 grid(384 / 128, MPAD / 128);
        k_gemm_mma<0><<<grid, 256>>>(p_Aaug, p_Baug, p_buf1, (__half*)0, 256, 384,
                                     b3, (const float*)0, (const float*)0,
                                     (const float*)0, (const float*)0);
    }
    // ---- pooling segments + mean+max pool ----
    k_scan_graphs<<<1, 1024>>>();
    k_pool<<<N_GRAPHS, 128>>>(p_buf1, out);
}